// round 1
// baseline (speedup 1.0000x reference)
#include <cuda_runtime.h>

// Problem constants (fixed by the dataset)
#define ND 128          // node feature dim
#define NMAX 50000
#define EMAX 640000
#define GMAX 1024
#define RDM 200
#define H1 512
#define H2 256
#define KMLP1 (ND + RDM)   // 328

// ---------------- scratch (device globals; no allocation allowed) ----------
__device__ float g_x0[NMAX * ND];
__device__ float g_agg[NMAX * ND];
__device__ float g_h[NMAX * ND];
__device__ float g_x1[NMAX * ND];
__device__ float g_x2[NMAX * ND];
__device__ float g_pool[GMAX * ND];
__device__ int   g_cnt[GMAX];
__device__ float g_min[GMAX * KMLP1];
__device__ float g_m1[GMAX * H1];
__device__ float g_m2[GMAX * H2];

// ---------------- packed f32x2 helpers (B300 2x-rate fp32 FMA) -------------
__device__ __forceinline__ unsigned long long pack2(float x, float y) {
    unsigned long long r;
    asm("mov.b64 %0, {%1, %2};" : "=l"(r) : "f"(x), "f"(y));
    return r;
}
__device__ __forceinline__ void unpack2(unsigned long long v, float& x, float& y) {
    asm("mov.b64 {%0, %1}, %2;" : "=f"(x), "=f"(y) : "l"(v));
}
__device__ __forceinline__ void ffma2(unsigned long long& d, unsigned long long a,
                                      unsigned long long b) {
    asm("fma.rn.f32x2 %0, %1, %2, %0;" : "+l"(d) : "l"(a), "l"(b));
}

// ---------------- kernel 1: atom encoder + graph-size histogram ------------
// one warp per node; lane handles 4 contiguous cols (float4)
__global__ void atom_encode_kernel(const int* __restrict__ xf,
                                   const int* __restrict__ batch,
                                   const float* __restrict__ aemb,
                                   float* __restrict__ xout, int N) {
    int warp = (blockIdx.x * blockDim.x + threadIdx.x) >> 5;
    int lane = threadIdx.x & 31;
    if (warp >= N) return;
    int n = warp;
    float4 acc = make_float4(0.f, 0.f, 0.f, 0.f);
#pragma unroll
    for (int f = 0; f < 9; f++) {
        int id = xf[n * 9 + f];
        const float4* row = reinterpret_cast<const float4*>(aemb + ((f << 6) + id) * ND);
        float4 v = row[lane];
        acc.x += v.x; acc.y += v.y; acc.z += v.z; acc.w += v.w;
    }
    reinterpret_cast<float4*>(xout + (size_t)n * ND)[lane] = acc;
    if (lane == 0) atomicAdd(&g_cnt[batch[n]], 1);
}

// ---------------- kernel 2: edge messages (gather + relu + scatter) --------
// one warp per edge; bond embedding recomputed from the 24KB table (L1-hot)
__global__ void edge_msg_kernel(const int* __restrict__ ei,
                                const int* __restrict__ eaf,
                                const float* __restrict__ bemb,
                                const float* __restrict__ xin,
                                float* __restrict__ agg, int E) {
    int warp = (blockIdx.x * blockDim.x + threadIdx.x) >> 5;
    int lane = threadIdx.x & 31;
    if (warp >= E) return;
    int e = warp;
    int src = ei[e];
    int dst = ei[E + e];
    int f0 = eaf[e * 3 + 0];
    int f1 = eaf[e * 3 + 1];
    int f2 = eaf[e * 3 + 2];
    const float4* b0 = reinterpret_cast<const float4*>(bemb + (0 * 16 + f0) * ND);
    const float4* b1 = reinterpret_cast<const float4*>(bemb + (1 * 16 + f1) * ND);
    const float4* b2 = reinterpret_cast<const float4*>(bemb + (2 * 16 + f2) * ND);
    float4 e0 = b0[lane], e1 = b1[lane], e2 = b2[lane];
    float4 xs = reinterpret_cast<const float4*>(xin + (size_t)src * ND)[lane];
    float mx = fmaxf(xs.x + e0.x + e1.x + e2.x, 0.f);
    float my = fmaxf(xs.y + e0.y + e1.y + e2.y, 0.f);
    float mz = fmaxf(xs.z + e0.z + e1.z + e2.z, 0.f);
    float mw = fmaxf(xs.w + e0.w + e1.w + e2.w, 0.f);
    float* dstp = agg + (size_t)dst * ND + lane * 4;
    atomicAdd(dstp + 0, mx);
    atomicAdd(dstp + 1, my);
    atomicAdd(dstp + 2, mz);
    atomicAdd(dstp + 3, mw);
}

// ---------------- tiled fp32 GEMM with f32x2 FMAs ---------------------------
// C[M,Nc] = act((A (+A2)) @ W + bias). K % BK == 0 required.
template <int BM, int BN, int BK, int TM, int TN, bool RELU>
__global__ void gemm_kernel(const float* __restrict__ A, const float* __restrict__ A2,
                            const float* __restrict__ W, const float* __restrict__ bias,
                            float* __restrict__ C, int M, int K, int Nc) {
    constexpr int THREADS = (BM / TM) * (BN / TN);
    __shared__ float sA[BK][BM + 4];   // transposed: sA[k][m]
    __shared__ float sW[BK][BN];

    const int tid = threadIdx.x;
    const int tn = tid % (BN / TN);
    const int tm = tid / (BN / TN);
    const int row0 = tm * TM;
    const int col0 = tn * TN;
    const int brow = blockIdx.x * BM;
    const int bcol = blockIdx.y * BN;

    unsigned long long acc[TM][TN / 2];
#pragma unroll
    for (int i = 0; i < TM; i++)
#pragma unroll
        for (int j = 0; j < TN / 2; j++) acc[i][j] = 0ull;

    for (int k0 = 0; k0 < K; k0 += BK) {
        // load A tile (BM x BK) as float4 along K, store transposed
        constexpr int A_LOADS = (BM * BK / 4) / THREADS;
#pragma unroll
        for (int i = 0; i < A_LOADS; i++) {
            int idx = tid + i * THREADS;
            int m = idx / (BK / 4);
            int kq = idx % (BK / 4);
            int grow = brow + m;
            float4 v = make_float4(0.f, 0.f, 0.f, 0.f);
            if (grow < M) {
                v = *reinterpret_cast<const float4*>(A + (size_t)grow * K + k0 + kq * 4);
                if (A2) {
                    float4 v2 = *reinterpret_cast<const float4*>(A2 + (size_t)grow * K + k0 + kq * 4);
                    v.x += v2.x; v.y += v2.y; v.z += v2.z; v.w += v2.w;
                }
            }
            sA[kq * 4 + 0][m] = v.x;
            sA[kq * 4 + 1][m] = v.y;
            sA[kq * 4 + 2][m] = v.z;
            sA[kq * 4 + 3][m] = v.w;
        }
        // load W tile (BK x BN)
        constexpr int W_LOADS = (BK * BN / 4) / THREADS;
#pragma unroll
        for (int i = 0; i < W_LOADS; i++) {
            int idx = tid + i * THREADS;
            int kk = idx / (BN / 4);
            int cq = idx % (BN / 4);
            *reinterpret_cast<float4*>(&sW[kk][cq * 4]) =
                *reinterpret_cast<const float4*>(W + (size_t)(k0 + kk) * Nc + bcol + cq * 4);
        }
        __syncthreads();

#pragma unroll
        for (int kk = 0; kk < BK; kk++) {
            float a[TM];
#pragma unroll
            for (int i = 0; i < TM; i += 4) {
                float4 t = *reinterpret_cast<const float4*>(&sA[kk][row0 + i]);
                a[i] = t.x; a[i + 1] = t.y; a[i + 2] = t.z; a[i + 3] = t.w;
            }
            unsigned long long wv[TN / 2];
#pragma unroll
            for (int j = 0; j < TN; j += 4) {
                float4 t = *reinterpret_cast<const float4*>(&sW[kk][col0 + j]);
                wv[j / 2] = pack2(t.x, t.y);
                wv[j / 2 + 1] = pack2(t.z, t.w);
            }
#pragma unroll
            for (int i = 0; i < TM; i++) {
                unsigned long long ad = pack2(a[i], a[i]);
#pragma unroll
                for (int j = 0; j < TN / 2; j++) ffma2(acc[i][j], ad, wv[j]);
            }
        }
        __syncthreads();
    }

    // epilogue
    float2 bv[TN / 2];
#pragma unroll
    for (int j = 0; j < TN / 2; j++)
        bv[j] = *reinterpret_cast<const float2*>(bias + bcol + col0 + 2 * j);
#pragma unroll
    for (int i = 0; i < TM; i++) {
        int grow = brow + row0 + i;
        if (grow >= M) continue;
#pragma unroll
        for (int j = 0; j < TN / 2; j++) {
            float x, y;
            unpack2(acc[i][j], x, y);
            x += bv[j].x; y += bv[j].y;
            if (RELU) { x = fmaxf(x, 0.f); y = fmaxf(y, 0.f); }
            float2 o; o.x = x; o.y = y;
            *reinterpret_cast<float2*>(C + (size_t)grow * Nc + bcol + col0 + 2 * j) = o;
        }
    }
}

// ---------------- pooling: sum per graph ------------------------------------
__global__ void pool_sum_kernel(const float* __restrict__ x,
                                const int* __restrict__ batch,
                                float* __restrict__ pool, int N) {
    int warp = (blockIdx.x * blockDim.x + threadIdx.x) >> 5;
    int lane = threadIdx.x & 31;
    if (warp >= N) return;
    int n = warp;
    int g = batch[n];
    float4 v = reinterpret_cast<const float4*>(x + (size_t)n * ND)[lane];
    float* p = pool + (size_t)g * ND + lane * 4;
    atomicAdd(p + 0, v.x);
    atomicAdd(p + 1, v.y);
    atomicAdd(p + 2, v.z);
    atomicAdd(p + 3, v.w);
}

// ---------------- concat: pooled mean + rdkit -------------------------------
__global__ void concat_kernel(const float* __restrict__ pool,
                              const float* __restrict__ rdkit,
                              float* __restrict__ out, int G) {
    int idx = blockIdx.x * blockDim.x + threadIdx.x;
    int total = G * KMLP1;
    if (idx >= total) return;
    int g = idx / KMLP1;
    int c = idx - g * KMLP1;
    float v;
    if (c < ND) {
        float cnt = (float)max(g_cnt[g], 1);
        v = pool[g * ND + c] / cnt;
    } else {
        v = rdkit[(size_t)g * RDM + (c - ND)];
    }
    out[idx] = v;
}

// ---------------- final layer: [G,256] @ [256,1] ----------------------------
__global__ void final_dot_kernel(const float* __restrict__ m2,
                                 const float* __restrict__ w3,
                                 const float* __restrict__ b3,
                                 float* __restrict__ out, int G) {
    int warp = (blockIdx.x * blockDim.x + threadIdx.x) >> 5;
    int lane = threadIdx.x & 31;
    if (warp >= G) return;
    int g = warp;
    float s = 0.f;
#pragma unroll
    for (int c = lane; c < H2; c += 32) s += m2[(size_t)g * H2 + c] * w3[c];
#pragma unroll
    for (int off = 16; off > 0; off >>= 1) s += __shfl_xor_sync(0xFFFFFFFFu, s, off);
    if (lane == 0) out[g] = s + b3[0];
}

// ---------------- launch ----------------------------------------------------
extern "C" void kernel_launch(void* const* d_in, const int* in_sizes, int n_in,
                              void* d_out, int out_size) {
    const int* x_feat     = (const int*)d_in[0];
    const int* edge_index = (const int*)d_in[1];
    const int* eaf        = (const int*)d_in[2];
    const int* batch      = (const int*)d_in[3];
    const float* rdkit    = (const float*)d_in[4];
    const float* atom_emb = (const float*)d_in[5];
    const float* bond_emb = (const float*)d_in[6];
    const float* c1w1 = (const float*)d_in[7];
    const float* c1b1 = (const float*)d_in[8];
    const float* c1w2 = (const float*)d_in[9];
    const float* c1b2 = (const float*)d_in[10];
    const float* c2w1 = (const float*)d_in[11];
    const float* c2b1 = (const float*)d_in[12];
    const float* c2w2 = (const float*)d_in[13];
    const float* c2b2 = (const float*)d_in[14];
    const float* mw1 = (const float*)d_in[15];
    const float* mb1 = (const float*)d_in[16];
    const float* mw2 = (const float*)d_in[17];
    const float* mb2 = (const float*)d_in[18];
    const float* mw3 = (const float*)d_in[19];
    const float* mb3 = (const float*)d_in[20];
    float* out = (float*)d_out;

    const int N = in_sizes[0] / 9;
    const int E = in_sizes[1] / 2;
    const int G = in_sizes[4] / RDM;

    float *p_x0, *p_agg, *p_h, *p_x1, *p_x2, *p_pool, *p_min, *p_m1, *p_m2;
    int* p_cnt;
    cudaGetSymbolAddress((void**)&p_x0, g_x0);
    cudaGetSymbolAddress((void**)&p_agg, g_agg);
    cudaGetSymbolAddress((void**)&p_h, g_h);
    cudaGetSymbolAddress((void**)&p_x1, g_x1);
    cudaGetSymbolAddress((void**)&p_x2, g_x2);
    cudaGetSymbolAddress((void**)&p_pool, g_pool);
    cudaGetSymbolAddress((void**)&p_cnt, g_cnt);
    cudaGetSymbolAddress((void**)&p_min, g_min);
    cudaGetSymbolAddress((void**)&p_m1, g_m1);
    cudaGetSymbolAddress((void**)&p_m2, g_m2);

    cudaMemsetAsync(p_cnt, 0, (size_t)G * sizeof(int), 0);

    // atom encoder (+ per-graph counts)
    {
        int warps = N;
        int blocks = (warps * 32 + 255) / 256;
        atom_encode_kernel<<<blocks, 256>>>(x_feat, batch, atom_emb, p_x0, N);
    }

    const int edge_blocks = (E * 32 + 255) / 256;
    const int gemm_blocks_m = (N + 127) / 128;

    // ---- conv1 ----
    cudaMemsetAsync(p_agg, 0, (size_t)N * ND * sizeof(float), 0);
    edge_msg_kernel<<<edge_blocks, 256>>>(edge_index, eaf, bond_emb, p_x0, p_agg, E);
    gemm_kernel<128, 128, 16, 8, 8, true><<<dim3(gemm_blocks_m, 1), 256>>>(
        p_x0, p_agg, c1w1, c1b1, p_h, N, ND, ND);
    gemm_kernel<128, 128, 16, 8, 8, false><<<dim3(gemm_blocks_m, 1), 256>>>(
        p_h, (const float*)nullptr, c1w2, c1b2, p_x1, N, ND, ND);

    // ---- conv2 ----
    cudaMemsetAsync(p_agg, 0, (size_t)N * ND * sizeof(float), 0);
    edge_msg_kernel<<<edge_blocks, 256>>>(edge_index, eaf, bond_emb, p_x1, p_agg, E);
    gemm_kernel<128, 128, 16, 8, 8, true><<<dim3(gemm_blocks_m, 1), 256>>>(
        p_x1, p_agg, c2w1, c2b1, p_h, N, ND, ND);
    gemm_kernel<128, 128, 16, 8, 8, false><<<dim3(gemm_blocks_m, 1), 256>>>(
        p_h, (const float*)nullptr, c2w2, c2b2, p_x2, N, ND, ND);

    // ---- pool + concat ----
    cudaMemsetAsync(p_pool, 0, (size_t)G * ND * sizeof(float), 0);
    {
        int blocks = (N * 32 + 255) / 256;
        pool_sum_kernel<<<blocks, 256>>>(p_x2, batch, p_pool, N);
    }
    {
        int total = G * KMLP1;
        concat_kernel<<<(total + 255) / 256, 256>>>(p_pool, rdkit, p_min, G);
    }

    // ---- MLP ----
    gemm_kernel<64, 64, 8, 4, 8, true><<<dim3(G / 64, H1 / 64), 128>>>(
        p_min, (const float*)nullptr, mw1, mb1, p_m1, G, KMLP1, H1);
    gemm_kernel<64, 64, 8, 4, 8, true><<<dim3(G / 64, H2 / 64), 128>>>(
        p_m1, (const float*)nullptr, mw2, mb2, p_m2, G, H1, H2);
    {
        int blocks = (G * 32 + 255) / 256;
        final_dot_kernel<<<blocks, 256>>>(p_m2, mw3, mb3, out, G);
    }
    (void)n_in; (void)out_size;
}

// round 2
// speedup vs baseline: 1.2823x; 1.2823x over previous
#include <cuda_runtime.h>

// Problem constants (fixed by the dataset)
#define ND 128          // node feature dim
#define NMAX 50000
#define EMAX 640000
#define GMAX 1024
#define RDM 200
#define H1 512
#define H2 256
#define KMLP1 (ND + RDM)   // 328

// ---------------- scratch (device globals; no allocation allowed) ----------
__device__ float g_x0[NMAX * ND];
__device__ float g_agg[NMAX * ND];
__device__ float g_h[NMAX * ND];
__device__ float g_x1[NMAX * ND];
__device__ float g_x2[NMAX * ND];
__device__ float g_pool[GMAX * ND];
__device__ int   g_cnt[GMAX];
__device__ float g_min[GMAX * KMLP1];
__device__ float g_m1[GMAX * H1];
__device__ float g_m2[GMAX * H2];

// ---------------- packed f32x2 helpers (B300 2x-rate fp32 FMA) -------------
__device__ __forceinline__ unsigned long long pack2(float x, float y) {
    unsigned long long r;
    asm("mov.b64 %0, {%1, %2};" : "=l"(r) : "f"(x), "f"(y));
    return r;
}
__device__ __forceinline__ void unpack2(unsigned long long v, float& x, float& y) {
    asm("mov.b64 {%0, %1}, %2;" : "=f"(x), "=f"(y) : "l"(v));
}
__device__ __forceinline__ void ffma2(unsigned long long& d, unsigned long long a,
                                      unsigned long long b) {
    asm("fma.rn.f32x2 %0, %1, %2, %0;" : "+l"(d) : "l"(a), "l"(b));
}
// vectorized no-return f32x4 reduction (sm_90+)
__device__ __forceinline__ void red_add_v4(float* p, float a, float b, float c, float d) {
    asm volatile("red.global.add.v4.f32 [%0], {%1, %2, %3, %4};"
                 :: "l"(p), "f"(a), "f"(b), "f"(c), "f"(d) : "memory");
}

// ---------------- kernel 1: atom encoder + graph-size histogram ------------
// one warp per node; lane handles 4 contiguous cols (float4)
__global__ void atom_encode_kernel(const int* __restrict__ xf,
                                   const int* __restrict__ batch,
                                   const float* __restrict__ aemb,
                                   float* __restrict__ xout, int N) {
    int warp = (blockIdx.x * blockDim.x + threadIdx.x) >> 5;
    int lane = threadIdx.x & 31;
    if (warp >= N) return;
    int n = warp;
    float4 acc = make_float4(0.f, 0.f, 0.f, 0.f);
#pragma unroll
    for (int f = 0; f < 9; f++) {
        int id = xf[n * 9 + f];
        const float4* row = reinterpret_cast<const float4*>(aemb + ((f << 6) + id) * ND);
        float4 v = row[lane];
        acc.x += v.x; acc.y += v.y; acc.z += v.z; acc.w += v.w;
    }
    reinterpret_cast<float4*>(xout + (size_t)n * ND)[lane] = acc;
    if (lane == 0) atomicAdd(&g_cnt[batch[n]], 1);
}

// ---------------- kernel 2: edge messages (gather + relu + scatter) --------
// one warp per edge; bond embedding recomputed from the 24KB table (L1-hot)
__global__ void edge_msg_kernel(const int* __restrict__ ei,
                                const int* __restrict__ eaf,
                                const float* __restrict__ bemb,
                                const float* __restrict__ xin,
                                float* __restrict__ agg, int E) {
    int warp = (blockIdx.x * blockDim.x + threadIdx.x) >> 5;
    int lane = threadIdx.x & 31;
    if (warp >= E) return;
    int e = warp;
    int src = ei[e];
    int dst = ei[E + e];
    int f0 = eaf[e * 3 + 0];
    int f1 = eaf[e * 3 + 1];
    int f2 = eaf[e * 3 + 2];
    const float4* b0 = reinterpret_cast<const float4*>(bemb + (0 * 16 + f0) * ND);
    const float4* b1 = reinterpret_cast<const float4*>(bemb + (1 * 16 + f1) * ND);
    const float4* b2 = reinterpret_cast<const float4*>(bemb + (2 * 16 + f2) * ND);
    float4 e0 = b0[lane], e1 = b1[lane], e2 = b2[lane];
    float4 xs = reinterpret_cast<const float4*>(xin + (size_t)src * ND)[lane];
    float mx = fmaxf(xs.x + e0.x + e1.x + e2.x, 0.f);
    float my = fmaxf(xs.y + e0.y + e1.y + e2.y, 0.f);
    float mz = fmaxf(xs.z + e0.z + e1.z + e2.z, 0.f);
    float mw = fmaxf(xs.w + e0.w + e1.w + e2.w, 0.f);
    float* dstp = agg + (size_t)dst * ND + lane * 4;
    red_add_v4(dstp, mx, my, mz, mw);
}

// ---------------- tiled fp32 GEMM with f32x2 FMAs ---------------------------
// C[M,Nc] = act((A (+A2)) @ W + bias). K % BK == 0 required.
template <int BM, int BN, int BK, int TM, int TN, bool RELU, int MINB>
__global__ void __launch_bounds__((BM / TM) * (BN / TN), MINB)
gemm_kernel(const float* __restrict__ A, const float* __restrict__ A2,
            const float* __restrict__ W, const float* __restrict__ bias,
            float* __restrict__ C, int M, int K, int Nc) {
    constexpr int THREADS = (BM / TM) * (BN / TN);
    __shared__ float sA[BK][BM + 4];   // transposed: sA[k][m]
    __shared__ float sW[BK][BN];

    const int tid = threadIdx.x;
    const int tn = tid % (BN / TN);
    const int tm = tid / (BN / TN);
    const int row0 = tm * TM;
    const int col0 = tn * TN;
    const int brow = blockIdx.x * BM;
    const int bcol = blockIdx.y * BN;

    unsigned long long acc[TM][TN / 2];
#pragma unroll
    for (int i = 0; i < TM; i++)
#pragma unroll
        for (int j = 0; j < TN / 2; j++) acc[i][j] = 0ull;

    for (int k0 = 0; k0 < K; k0 += BK) {
        // load A tile (BM x BK) as float4 along K, store transposed
        constexpr int A_LOADS = (BM * BK / 4) / THREADS;
#pragma unroll
        for (int i = 0; i < A_LOADS; i++) {
            int idx = tid + i * THREADS;
            int m = idx / (BK / 4);
            int kq = idx % (BK / 4);
            int grow = brow + m;
            float4 v = make_float4(0.f, 0.f, 0.f, 0.f);
            if (grow < M) {
                v = *reinterpret_cast<const float4*>(A + (size_t)grow * K + k0 + kq * 4);
                if (A2) {
                    float4 v2 = *reinterpret_cast<const float4*>(A2 + (size_t)grow * K + k0 + kq * 4);
                    v.x += v2.x; v.y += v2.y; v.z += v2.z; v.w += v2.w;
                }
            }
            sA[kq * 4 + 0][m] = v.x;
            sA[kq * 4 + 1][m] = v.y;
            sA[kq * 4 + 2][m] = v.z;
            sA[kq * 4 + 3][m] = v.w;
        }
        // load W tile (BK x BN)
        constexpr int W_LOADS = (BK * BN / 4) / THREADS;
#pragma unroll
        for (int i = 0; i < W_LOADS; i++) {
            int idx = tid + i * THREADS;
            int kk = idx / (BN / 4);
            int cq = idx % (BN / 4);
            *reinterpret_cast<float4*>(&sW[kk][cq * 4]) =
                *reinterpret_cast<const float4*>(W + (size_t)(k0 + kk) * Nc + bcol + cq * 4);
        }
        __syncthreads();

#pragma unroll
        for (int kk = 0; kk < BK; kk++) {
            float a[TM];
#pragma unroll
            for (int i = 0; i < TM; i += 4) {
                float4 t = *reinterpret_cast<const float4*>(&sA[kk][row0 + i]);
                a[i] = t.x; a[i + 1] = t.y; a[i + 2] = t.z; a[i + 3] = t.w;
            }
            unsigned long long wv[TN / 2];
#pragma unroll
            for (int j = 0; j < TN; j += 4) {
                float4 t = *reinterpret_cast<const float4*>(&sW[kk][col0 + j]);
                wv[j / 2] = pack2(t.x, t.y);
                wv[j / 2 + 1] = pack2(t.z, t.w);
            }
#pragma unroll
            for (int i = 0; i < TM; i++) {
                unsigned long long ad = pack2(a[i], a[i]);
#pragma unroll
                for (int j = 0; j < TN / 2; j++) ffma2(acc[i][j], ad, wv[j]);
            }
        }
        __syncthreads();
    }

    // epilogue
    float2 bv[TN / 2];
#pragma unroll
    for (int j = 0; j < TN / 2; j++)
        bv[j] = *reinterpret_cast<const float2*>(bias + bcol + col0 + 2 * j);
#pragma unroll
    for (int i = 0; i < TM; i++) {
        int grow = brow + row0 + i;
        if (grow >= M) continue;
#pragma unroll
        for (int j = 0; j < TN / 2; j++) {
            float x, y;
            unpack2(acc[i][j], x, y);
            x += bv[j].x; y += bv[j].y;
            if (RELU) { x = fmaxf(x, 0.f); y = fmaxf(y, 0.f); }
            float2 o; o.x = x; o.y = y;
            *reinterpret_cast<float2*>(C + (size_t)grow * Nc + bcol + col0 + 2 * j) = o;
        }
    }
}

// ---------------- pooling: sum per graph ------------------------------------
__global__ void pool_sum_kernel(const float* __restrict__ x,
                                const int* __restrict__ batch,
                                float* __restrict__ pool, int N) {
    int warp = (blockIdx.x * blockDim.x + threadIdx.x) >> 5;
    int lane = threadIdx.x & 31;
    if (warp >= N) return;
    int n = warp;
    int g = batch[n];
    float4 v = reinterpret_cast<const float4*>(x + (size_t)n * ND)[lane];
    float* p = pool + (size_t)g * ND + lane * 4;
    red_add_v4(p, v.x, v.y, v.z, v.w);
}

// ---------------- concat: pooled mean + rdkit -------------------------------
__global__ void concat_kernel(const float* __restrict__ pool,
                              const float* __restrict__ rdkit,
                              float* __restrict__ out, int G) {
    int idx = blockIdx.x * blockDim.x + threadIdx.x;
    int total = G * KMLP1;
    if (idx >= total) return;
    int g = idx / KMLP1;
    int c = idx - g * KMLP1;
    float v;
    if (c < ND) {
        float cnt = (float)max(g_cnt[g], 1);
        v = pool[g * ND + c] / cnt;
    } else {
        v = rdkit[(size_t)g * RDM + (c - ND)];
    }
    out[idx] = v;
}

// ---------------- final layer: [G,256] @ [256,1] ----------------------------
__global__ void final_dot_kernel(const float* __restrict__ m2,
                                 const float* __restrict__ w3,
                                 const float* __restrict__ b3,
                                 float* __restrict__ out, int G) {
    int warp = (blockIdx.x * blockDim.x + threadIdx.x) >> 5;
    int lane = threadIdx.x & 31;
    if (warp >= G) return;
    int g = warp;
    float s = 0.f;
#pragma unroll
    for (int c = lane; c < H2; c += 32) s += m2[(size_t)g * H2 + c] * w3[c];
#pragma unroll
    for (int off = 16; off > 0; off >>= 1) s += __shfl_xor_sync(0xFFFFFFFFu, s, off);
    if (lane == 0) out[g] = s + b3[0];
}

// ---------------- launch ----------------------------------------------------
extern "C" void kernel_launch(void* const* d_in, const int* in_sizes, int n_in,
                              void* d_out, int out_size) {
    const int* x_feat     = (const int*)d_in[0];
    const int* edge_index = (const int*)d_in[1];
    const int* eaf        = (const int*)d_in[2];
    const int* batch      = (const int*)d_in[3];
    const float* rdkit    = (const float*)d_in[4];
    const float* atom_emb = (const float*)d_in[5];
    const float* bond_emb = (const float*)d_in[6];
    const float* c1w1 = (const float*)d_in[7];
    const float* c1b1 = (const float*)d_in[8];
    const float* c1w2 = (const float*)d_in[9];
    const float* c1b2 = (const float*)d_in[10];
    const float* c2w1 = (const float*)d_in[11];
    const float* c2b1 = (const float*)d_in[12];
    const float* c2w2 = (const float*)d_in[13];
    const float* c2b2 = (const float*)d_in[14];
    const float* mw1 = (const float*)d_in[15];
    const float* mb1 = (const float*)d_in[16];
    const float* mw2 = (const float*)d_in[17];
    const float* mb2 = (const float*)d_in[18];
    const float* mw3 = (const float*)d_in[19];
    const float* mb3 = (const float*)d_in[20];
    float* out = (float*)d_out;

    const int N = in_sizes[0] / 9;
    const int E = in_sizes[1] / 2;
    const int G = in_sizes[4] / RDM;

    float *p_x0, *p_agg, *p_h, *p_x1, *p_x2, *p_pool, *p_min, *p_m1, *p_m2;
    int* p_cnt;
    cudaGetSymbolAddress((void**)&p_x0, g_x0);
    cudaGetSymbolAddress((void**)&p_agg, g_agg);
    cudaGetSymbolAddress((void**)&p_h, g_h);
    cudaGetSymbolAddress((void**)&p_x1, g_x1);
    cudaGetSymbolAddress((void**)&p_x2, g_x2);
    cudaGetSymbolAddress((void**)&p_pool, g_pool);
    cudaGetSymbolAddress((void**)&p_cnt, g_cnt);
    cudaGetSymbolAddress((void**)&p_min, g_min);
    cudaGetSymbolAddress((void**)&p_m1, g_m1);
    cudaGetSymbolAddress((void**)&p_m2, g_m2);

    cudaMemsetAsync(p_cnt, 0, (size_t)G * sizeof(int), 0);

    // atom encoder (+ per-graph counts)
    {
        int warps = N;
        int blocks = (warps * 32 + 255) / 256;
        atom_encode_kernel<<<blocks, 256>>>(x_feat, batch, atom_emb, p_x0, N);
    }

    const int edge_blocks = (E * 32 + 255) / 256;
    const int gemm_blocks_m = (N + 63) / 64;   // BM=64 for conv GEMMs

    // ---- conv1 ----
    cudaMemsetAsync(p_agg, 0, (size_t)N * ND * sizeof(float), 0);
    edge_msg_kernel<<<edge_blocks, 256>>>(edge_index, eaf, bond_emb, p_x0, p_agg, E);
    gemm_kernel<64, 128, 16, 4, 8, true, 3><<<dim3(gemm_blocks_m, 1), 256>>>(
        p_x0, p_agg, c1w1, c1b1, p_h, N, ND, ND);
    gemm_kernel<64, 128, 16, 4, 8, false, 3><<<dim3(gemm_blocks_m, 1), 256>>>(
        p_h, (const float*)nullptr, c1w2, c1b2, p_x1, N, ND, ND);

    // ---- conv2 ----
    cudaMemsetAsync(p_agg, 0, (size_t)N * ND * sizeof(float), 0);
    edge_msg_kernel<<<edge_blocks, 256>>>(edge_index, eaf, bond_emb, p_x1, p_agg, E);
    gemm_kernel<64, 128, 16, 4, 8, true, 3><<<dim3(gemm_blocks_m, 1), 256>>>(
        p_x1, p_agg, c2w1, c2b1, p_h, N, ND, ND);
    gemm_kernel<64, 128, 16, 4, 8, false, 3><<<dim3(gemm_blocks_m, 1), 256>>>(
        p_h, (const float*)nullptr, c2w2, c2b2, p_x2, N, ND, ND);

    // ---- pool + concat ----
    cudaMemsetAsync(p_pool, 0, (size_t)G * ND * sizeof(float), 0);
    {
        int blocks = (N * 32 + 255) / 256;
        pool_sum_kernel<<<blocks, 256>>>(p_x2, batch, p_pool, N);
    }
    {
        int total = G * KMLP1;
        concat_kernel<<<(total + 255) / 256, 256>>>(p_pool, rdkit, p_min, G);
    }

    // ---- MLP ----
    gemm_kernel<64, 64, 8, 4, 8, true, 1><<<dim3(G / 64, H1 / 64), 128>>>(
        p_min, (const float*)nullptr, mw1, mb1, p_m1, G, KMLP1, H1);
    gemm_kernel<64, 64, 8, 4, 8, true, 1><<<dim3(G / 64, H2 / 64), 128>>>(
        p_m1, (const float*)nullptr, mw2, mb2, p_m2, G, H1, H2);
    {
        int blocks = (G * 32 + 255) / 256;
        final_dot_kernel<<<blocks, 256>>>(p_m2, mw3, mb3, out, G);
    }
    (void)n_in; (void)out_size;
}

// round 4
// speedup vs baseline: 1.7841x; 1.3914x over previous
#include <cuda_runtime.h>
#include <cuda_bf16.h>
#include <cstdint>

// Problem constants (fixed by the dataset)
#define ND 128
#define NMAX 50000
#define EMAX 640000
#define GMAX 1024
#define RDM 200
#define H1 512
#define H2 256
#define KMLP1 (ND + RDM)   // 328

// ---------------- scratch (device globals; no allocation allowed) ----------
__device__ float g_x0[NMAX * ND];
__device__ float g_agg[NMAX * ND];
__device__ float g_h[NMAX * ND];
__device__ float g_x1[NMAX * ND];
__device__ float g_x2[NMAX * ND];
__device__ float g_pool[GMAX * ND];
__device__ int   g_cnt[GMAX];
__device__ float g_min[GMAX * KMLP1];
__device__ float g_m1[GMAX * H1];
__device__ float g_m2[GMAX * H2];
// prepped conv weights: per matrix 64KB = Wt hi (32KB) + Wt lo (32KB), [n][k] bf16
__device__ uint4 g_wp[4][4096];

// ---------------- helpers ----------------------------------------------------
__device__ __forceinline__ unsigned long long pack2(float x, float y) {
    unsigned long long r;
    asm("mov.b64 %0, {%1, %2};" : "=l"(r) : "f"(x), "f"(y));
    return r;
}
__device__ __forceinline__ void unpack2(unsigned long long v, float& x, float& y) {
    asm("mov.b64 {%0, %1}, %2;" : "=f"(x), "=f"(y) : "l"(v));
}
__device__ __forceinline__ void ffma2(unsigned long long& d, unsigned long long a,
                                      unsigned long long b) {
    asm("fma.rn.f32x2 %0, %1, %2, %0;" : "+l"(d) : "l"(a), "l"(b));
}
__device__ __forceinline__ void red_add_v4(float* p, float a, float b, float c, float d) {
    asm volatile("red.global.add.v4.f32 [%0], {%1, %2, %3, %4};"
                 :: "l"(p), "f"(a), "f"(b), "f"(c), "f"(d) : "memory");
}
// hi/lo bf16x2 split of two floats (a=elem0/low half, b=elem1/high half)
__device__ __forceinline__ uint32_t hilo(float a, float b, uint32_t& lopack) {
    uint32_t h;
    asm("cvt.rn.bf16x2.f32 %0, %1, %2;" : "=r"(h) : "f"(b), "f"(a));
    float fa = __uint_as_float(h << 16);
    float fb = __uint_as_float(h & 0xffff0000u);
    float ra = a - fa, rb = b - fb;
    uint32_t l;
    asm("cvt.rn.bf16x2.f32 %0, %1, %2;" : "=r"(l) : "f"(rb), "f"(ra));
    lopack = l;
    return h;
}
// warp-level bf16 tensor-core mma (baseline PTX, works on plain sm_103)
__device__ __forceinline__ void mma16816(float* c, const uint32_t* a, const uint32_t* b) {
    asm volatile(
        "mma.sync.aligned.m16n8k16.row.col.f32.bf16.bf16.f32 "
        "{%0,%1,%2,%3}, {%4,%5,%6,%7}, {%8,%9}, {%0,%1,%2,%3};"
        : "+f"(c[0]), "+f"(c[1]), "+f"(c[2]), "+f"(c[3])
        : "r"(a[0]), "r"(a[1]), "r"(a[2]), "r"(a[3]), "r"(b[0]), "r"(b[1]));
}

// ---------------- kernel: W prep (transpose + hi/lo bf16 split) -------------
// writes Wt[n][k] row-major bf16: hi at [0,32768)B, lo at [32768,65536)B
__global__ void wprep_kernel(const float* __restrict__ w0, const float* __restrict__ w1,
                             const float* __restrict__ w2, const float* __restrict__ w3) {
    int widx = blockIdx.x >> 6;
    int idx = (blockIdx.x & 63) * 256 + threadIdx.x;   // 0..16383
    const float* W = (widx == 0) ? w0 : (widx == 1) ? w1 : (widx == 2) ? w2 : w3;
    int n = idx >> 7, k = idx & 127;
    float w = W[k * 128 + n];
    __nv_bfloat16 h = __float2bfloat16(w);
    float r = w - __bfloat162float(h);
    __nv_bfloat16 l = __float2bfloat16(r);
    char* base = (char*)&g_wp[widx][0];
    uint32_t off = (uint32_t)(n * 128 + k) * 2u;
    *(__nv_bfloat16*)(base + off) = h;
    *(__nv_bfloat16*)(base + 32768 + off) = l;
}

// ---------------- kernel: tensor-core conv GEMM ------------------------------
// C[M,128] = act((A (+A2)) @ W + bias), bf16x3 split, fp32 accumulate.
// CTA: 256 threads = 8 warps (4 m-blocks x 2 n-blocks), tile 128x128, K=128.
#define SAK 136   // padded bf16 stride (272B = 17*16B: 16B-aligned rows, +4 banks/row)
#define TCSM (4 * 128 * SAK * 2)   // 4 tiles (Ahi, Alo, Whi, Wlo) = 139264 B

template <bool RELU, bool HASA2>
__global__ void __launch_bounds__(256, 1)
gemm_mma_kernel(const float* __restrict__ A, const float* __restrict__ A2,
                const uint4* __restrict__ Wp, const float* __restrict__ bias,
                float* __restrict__ C, int M) {
    extern __shared__ char dsm[];
    __shared__ float s_bias[128];

    char* pAhi = dsm;
    char* pAlo = dsm + 128 * SAK * 2;
    char* pWhi = dsm + 2 * 128 * SAK * 2;
    char* pWlo = dsm + 3 * 128 * SAK * 2;
    const uint32_t* sAhi = (const uint32_t*)pAhi;
    const uint32_t* sAlo = (const uint32_t*)pAlo;
    const uint32_t* sWhi = (const uint32_t*)pWhi;
    const uint32_t* sWlo = (const uint32_t*)pWlo;

    const int tid = threadIdx.x, wid = tid >> 5, lane = tid & 31;
    const int g = lane >> 2, q = lane & 3;
    const int wm = wid & 3, wn = wid >> 2;
    const int brow = blockIdx.x * 128;

    if (tid < 128) s_bias[tid] = bias[tid];

    // ---- stage W: global (packed [n][k]) -> smem (padded rows) ----
    {
#pragma unroll
        for (int i = 0; i < 8; i++) {
            int u = tid + i * 256;              // 0..2047 (hi chain)
            int n = u >> 4, kc = (u & 15);      // kc*8 = k offset
            uint4 vh = Wp[u];
            uint4 vl = Wp[u + 2048];
            *(uint4*)(pWhi + n * (SAK * 2) + kc * 16) = vh;
            *(uint4*)(pWlo + n * (SAK * 2) + kc * 16) = vl;
        }
    }

    // ---- stage A (+A2): fp32 -> hi/lo bf16 ----
    {
        int row = tid >> 1;
        int c0 = (tid & 1) * 64;
        bool valid = (brow + row) < M;
        const float4* a4 = (const float4*)(A + (size_t)(brow + row) * 128 + c0);
        const float4* b4 = (const float4*)(HASA2 ? (A2 + (size_t)(brow + row) * 128 + c0)
                                                 : (const float*)nullptr);
        char* dAh = pAhi + row * (SAK * 2) + c0 * 2;
        char* dAl = pAlo + row * (SAK * 2) + c0 * 2;
#pragma unroll
        for (int i = 0; i < 8; i++) {
            float4 v0 = make_float4(0.f, 0.f, 0.f, 0.f), v1 = v0;
            if (valid) {
                v0 = a4[i * 2]; v1 = a4[i * 2 + 1];
                if (HASA2) {
                    float4 w0 = b4[i * 2], w1 = b4[i * 2 + 1];
                    v0.x += w0.x; v0.y += w0.y; v0.z += w0.z; v0.w += w0.w;
                    v1.x += w1.x; v1.y += w1.y; v1.z += w1.z; v1.w += w1.w;
                }
            }
            uint4 h, l;
            h.x = hilo(v0.x, v0.y, l.x);
            h.y = hilo(v0.z, v0.w, l.y);
            h.z = hilo(v1.x, v1.y, l.z);
            h.w = hilo(v1.z, v1.w, l.w);
            *(uint4*)(dAh + i * 16) = h;
            *(uint4*)(dAl + i * 16) = l;
        }
    }
    __syncthreads();

    // ---- main loop: 8 k-steps x 3 chains ----
    float acc[2][8][4];
#pragma unroll
    for (int mt = 0; mt < 2; mt++)
#pragma unroll
        for (int nt = 0; nt < 8; nt++)
#pragma unroll
            for (int j = 0; j < 4; j++) acc[mt][nt][j] = 0.f;

    const int ra0 = wm * 32 + g;       // A row for this lane (mt adds 16)
    const int nb0 = wn * 64 + g;       // B n for this lane (nt adds 8)

#pragma unroll
    for (int ks = 0; ks < 8; ks++) {
        const int k0 = ks * 16 + q * 2;
        // A fragments for both m-tiles, both chains
        uint32_t ah[2][4], al[2][4];
#pragma unroll
        for (int mt = 0; mt < 2; mt++) {
            int r = ra0 + mt * 16;
            int i00 = (r * SAK + k0) >> 1;
            int i10 = ((r + 8) * SAK + k0) >> 1;
            ah[mt][0] = sAhi[i00];     ah[mt][1] = sAhi[i10];
            ah[mt][2] = sAhi[i00 + 4]; ah[mt][3] = sAhi[i10 + 4];
            al[mt][0] = sAlo[i00];     al[mt][1] = sAlo[i10];
            al[mt][2] = sAlo[i00 + 4]; al[mt][3] = sAlo[i10 + 4];
        }
#pragma unroll
        for (int nt = 0; nt < 8; nt++) {
            int n = nb0 + nt * 8;
            int ib = (n * SAK + k0) >> 1;
            uint32_t bh[2], bl[2];
            bh[0] = sWhi[ib]; bh[1] = sWhi[ib + 4];
            bl[0] = sWlo[ib]; bl[1] = sWlo[ib + 4];
#pragma unroll
            for (int mt = 0; mt < 2; mt++) {
                mma16816(acc[mt][nt], ah[mt], bh);
                mma16816(acc[mt][nt], al[mt], bh);
                mma16816(acc[mt][nt], ah[mt], bl);
            }
        }
    }

    // ---- epilogue ----
#pragma unroll
    for (int mt = 0; mt < 2; mt++) {
        int r0 = brow + wm * 32 + mt * 16 + g;
#pragma unroll
        for (int nt = 0; nt < 8; nt++) {
            int col = wn * 64 + nt * 8 + q * 2;
            float bx = s_bias[col], by = s_bias[col + 1];
            float x0 = acc[mt][nt][0] + bx, y0 = acc[mt][nt][1] + by;
            float x1 = acc[mt][nt][2] + bx, y1 = acc[mt][nt][3] + by;
            if (RELU) {
                x0 = fmaxf(x0, 0.f); y0 = fmaxf(y0, 0.f);
                x1 = fmaxf(x1, 0.f); y1 = fmaxf(y1, 0.f);
            }
            if (r0 < M) {
                float2 o; o.x = x0; o.y = y0;
                *(float2*)(C + (size_t)r0 * 128 + col) = o;
            }
            if (r0 + 8 < M) {
                float2 o; o.x = x1; o.y = y1;
                *(float2*)(C + (size_t)(r0 + 8) * 128 + col) = o;
            }
        }
    }
}

// ---------------- kernel: atom encoder + graph-size histogram ---------------
__global__ void atom_encode_kernel(const int* __restrict__ xf,
                                   const int* __restrict__ batch,
                                   const float* __restrict__ aemb,
                                   float* __restrict__ xout, int N) {
    int warp = (blockIdx.x * blockDim.x + threadIdx.x) >> 5;
    int lane = threadIdx.x & 31;
    if (warp >= N) return;
    int n = warp;
    float4 acc = make_float4(0.f, 0.f, 0.f, 0.f);
#pragma unroll
    for (int f = 0; f < 9; f++) {
        int id = xf[n * 9 + f];
        const float4* row = reinterpret_cast<const float4*>(aemb + ((f << 6) + id) * ND);
        float4 v = row[lane];
        acc.x += v.x; acc.y += v.y; acc.z += v.z; acc.w += v.w;
    }
    reinterpret_cast<float4*>(xout + (size_t)n * ND)[lane] = acc;
    if (lane == 0) atomicAdd(&g_cnt[batch[n]], 1);
}

// ---------------- kernel: edge messages (gather + relu + scatter) -----------
__global__ void edge_msg_kernel(const int* __restrict__ ei,
                                const int* __restrict__ eaf,
                                const float* __restrict__ bemb,
                                const float* __restrict__ xin,
                                float* __restrict__ agg, int E) {
    int warp = (blockIdx.x * blockDim.x + threadIdx.x) >> 5;
    int lane = threadIdx.x & 31;
    if (warp >= E) return;
    int e = warp;
    int src = ei[e];
    int dst = ei[E + e];
    int f0 = eaf[e * 3 + 0];
    int f1 = eaf[e * 3 + 1];
    int f2 = eaf[e * 3 + 2];
    const float4* b0 = reinterpret_cast<const float4*>(bemb + (0 * 16 + f0) * ND);
    const float4* b1 = reinterpret_cast<const float4*>(bemb + (1 * 16 + f1) * ND);
    const float4* b2 = reinterpret_cast<const float4*>(bemb + (2 * 16 + f2) * ND);
    float4 e0 = b0[lane], e1 = b1[lane], e2 = b2[lane];
    float4 xs = reinterpret_cast<const float4*>(xin + (size_t)src * ND)[lane];
    float mx = fmaxf(xs.x + e0.x + e1.x + e2.x, 0.f);
    float my = fmaxf(xs.y + e0.y + e1.y + e2.y, 0.f);
    float mz = fmaxf(xs.z + e0.z + e1.z + e2.z, 0.f);
    float mw = fmaxf(xs.w + e0.w + e1.w + e2.w, 0.f);
    float* dstp = agg + (size_t)dst * ND + lane * 4;
    red_add_v4(dstp, mx, my, mz, mw);
}

// ---------------- fp32 GEMM (MLP only) --------------------------------------
template <int BM, int BN, int BK, int TM, int TN, bool RELU, int MINB>
__global__ void __launch_bounds__((BM / TM) * (BN / TN), MINB)
gemm_kernel(const float* __restrict__ A, const float* __restrict__ A2,
            const float* __restrict__ W, const float* __restrict__ bias,
            float* __restrict__ C, int M, int K, int Nc) {
    constexpr int THREADS = (BM / TM) * (BN / TN);
    __shared__ float sA[BK][BM + 4];
    __shared__ float sW[BK][BN];

    const int tid = threadIdx.x;
    const int tn = tid % (BN / TN);
    const int tm = tid / (BN / TN);
    const int row0 = tm * TM;
    const int col0 = tn * TN;
    const int brow = blockIdx.x * BM;
    const int bcol = blockIdx.y * BN;

    unsigned long long acc[TM][TN / 2];
#pragma unroll
    for (int i = 0; i < TM; i++)
#pragma unroll
        for (int j = 0; j < TN / 2; j++) acc[i][j] = 0ull;

    for (int k0 = 0; k0 < K; k0 += BK) {
        constexpr int A_LOADS = (BM * BK / 4) / THREADS;
#pragma unroll
        for (int i = 0; i < A_LOADS; i++) {
            int idx = tid + i * THREADS;
            int m = idx / (BK / 4);
            int kq = idx % (BK / 4);
            int grow = brow + m;
            float4 v = make_float4(0.f, 0.f, 0.f, 0.f);
            if (grow < M) {
                v = *reinterpret_cast<const float4*>(A + (size_t)grow * K + k0 + kq * 4);
                if (A2) {
                    float4 v2 = *reinterpret_cast<const float4*>(A2 + (size_t)grow * K + k0 + kq * 4);
                    v.x += v2.x; v.y += v2.y; v.z += v2.z; v.w += v2.w;
                }
            }
            sA[kq * 4 + 0][m] = v.x;
            sA[kq * 4 + 1][m] = v.y;
            sA[kq * 4 + 2][m] = v.z;
            sA[kq * 4 + 3][m] = v.w;
        }
        constexpr int W_LOADS = (BK * BN / 4) / THREADS;
#pragma unroll
        for (int i = 0; i < W_LOADS; i++) {
            int idx = tid + i * THREADS;
            int kk = idx / (BN / 4);
            int cq = idx % (BN / 4);
            *reinterpret_cast<float4*>(&sW[kk][cq * 4]) =
                *reinterpret_cast<const float4*>(W + (size_t)(k0 + kk) * Nc + bcol + cq * 4);
        }
        __syncthreads();

#pragma unroll
        for (int kk = 0; kk < BK; kk++) {
            float a[TM];
#pragma unroll
            for (int i = 0; i < TM; i += 4) {
                float4 t = *reinterpret_cast<const float4*>(&sA[kk][row0 + i]);
                a[i] = t.x; a[i + 1] = t.y; a[i + 2] = t.z; a[i + 3] = t.w;
            }
            unsigned long long wv[TN / 2];
#pragma unroll
            for (int j = 0; j < TN; j += 4) {
                float4 t = *reinterpret_cast<const float4*>(&sW[kk][col0 + j]);
                wv[j / 2] = pack2(t.x, t.y);
                wv[j / 2 + 1] = pack2(t.z, t.w);
            }
#pragma unroll
            for (int i = 0; i < TM; i++) {
                unsigned long long ad = pack2(a[i], a[i]);
#pragma unroll
                for (int j = 0; j < TN / 2; j++) ffma2(acc[i][j], ad, wv[j]);
            }
        }
        __syncthreads();
    }

    float2 bv[TN / 2];
#pragma unroll
    for (int j = 0; j < TN / 2; j++)
        bv[j] = *reinterpret_cast<const float2*>(bias + bcol + col0 + 2 * j);
#pragma unroll
    for (int i = 0; i < TM; i++) {
        int grow = brow + row0 + i;
        if (grow >= M) continue;
#pragma unroll
        for (int j = 0; j < TN / 2; j++) {
            float x, y;
            unpack2(acc[i][j], x, y);
            x += bv[j].x; y += bv[j].y;
            if (RELU) { x = fmaxf(x, 0.f); y = fmaxf(y, 0.f); }
            float2 o; o.x = x; o.y = y;
            *reinterpret_cast<float2*>(C + (size_t)grow * Nc + bcol + col0 + 2 * j) = o;
        }
    }
}

// ---------------- pooling: sum per graph -------------------------------------
__global__ void pool_sum_kernel(const float* __restrict__ x,
                                const int* __restrict__ batch,
                                float* __restrict__ pool, int N) {
    int warp = (blockIdx.x * blockDim.x + threadIdx.x) >> 5;
    int lane = threadIdx.x & 31;
    if (warp >= N) return;
    int n = warp;
    int g = batch[n];
    float4 v = reinterpret_cast<const float4*>(x + (size_t)n * ND)[lane];
    float* p = pool + (size_t)g * ND + lane * 4;
    red_add_v4(p, v.x, v.y, v.z, v.w);
}

// ---------------- concat: pooled mean + rdkit --------------------------------
__global__ void concat_kernel(const float* __restrict__ pool,
                              const float* __restrict__ rdkit,
                              float* __restrict__ out, int G) {
    int idx = blockIdx.x * blockDim.x + threadIdx.x;
    int total = G * KMLP1;
    if (idx >= total) return;
    int g = idx / KMLP1;
    int c = idx - g * KMLP1;
    float v;
    if (c < ND) {
        float cnt = (float)max(g_cnt[g], 1);
        v = pool[g * ND + c] / cnt;
    } else {
        v = rdkit[(size_t)g * RDM + (c - ND)];
    }
    out[idx] = v;
}

// ---------------- final layer: [G,256] @ [256,1] -----------------------------
__global__ void final_dot_kernel(const float* __restrict__ m2,
                                 const float* __restrict__ w3,
                                 const float* __restrict__ b3,
                                 float* __restrict__ out, int G) {
    int warp = (blockIdx.x * blockDim.x + threadIdx.x) >> 5;
    int lane = threadIdx.x & 31;
    if (warp >= G) return;
    int g = warp;
    float s = 0.f;
#pragma unroll
    for (int c = lane; c < H2; c += 32) s += m2[(size_t)g * H2 + c] * w3[c];
#pragma unroll
    for (int off = 16; off > 0; off >>= 1) s += __shfl_xor_sync(0xFFFFFFFFu, s, off);
    if (lane == 0) out[g] = s + b3[0];
}

// ---------------- launch ------------------------------------------------------
extern "C" void kernel_launch(void* const* d_in, const int* in_sizes, int n_in,
                              void* d_out, int out_size) {
    const int* x_feat     = (const int*)d_in[0];
    const int* edge_index = (const int*)d_in[1];
    const int* eaf        = (const int*)d_in[2];
    const int* batch      = (const int*)d_in[3];
    const float* rdkit    = (const float*)d_in[4];
    const float* atom_emb = (const float*)d_in[5];
    const float* bond_emb = (const float*)d_in[6];
    const float* c1w1 = (const float*)d_in[7];
    const float* c1b1 = (const float*)d_in[8];
    const float* c1w2 = (const float*)d_in[9];
    const float* c1b2 = (const float*)d_in[10];
    const float* c2w1 = (const float*)d_in[11];
    const float* c2b1 = (const float*)d_in[12];
    const float* c2w2 = (const float*)d_in[13];
    const float* c2b2 = (const float*)d_in[14];
    const float* mw1 = (const float*)d_in[15];
    const float* mb1 = (const float*)d_in[16];
    const float* mw2 = (const float*)d_in[17];
    const float* mb2 = (const float*)d_in[18];
    const float* mw3 = (const float*)d_in[19];
    const float* mb3 = (const float*)d_in[20];
    float* out = (float*)d_out;

    const int N = in_sizes[0] / 9;
    const int E = in_sizes[1] / 2;
    const int G = in_sizes[4] / RDM;

    float *p_x0, *p_agg, *p_h, *p_x1, *p_x2, *p_pool, *p_min, *p_m1, *p_m2;
    int* p_cnt;
    uint4* p_wp;
    cudaGetSymbolAddress((void**)&p_x0, g_x0);
    cudaGetSymbolAddress((void**)&p_agg, g_agg);
    cudaGetSymbolAddress((void**)&p_h, g_h);
    cudaGetSymbolAddress((void**)&p_x1, g_x1);
    cudaGetSymbolAddress((void**)&p_x2, g_x2);
    cudaGetSymbolAddress((void**)&p_pool, g_pool);
    cudaGetSymbolAddress((void**)&p_cnt, g_cnt);
    cudaGetSymbolAddress((void**)&p_min, g_min);
    cudaGetSymbolAddress((void**)&p_m1, g_m1);
    cudaGetSymbolAddress((void**)&p_m2, g_m2);
    cudaGetSymbolAddress((void**)&p_wp, g_wp);

    cudaFuncSetAttribute(gemm_mma_kernel<true, true>,
                         cudaFuncAttributeMaxDynamicSharedMemorySize, TCSM);
    cudaFuncSetAttribute(gemm_mma_kernel<false, false>,
                         cudaFuncAttributeMaxDynamicSharedMemorySize, TCSM);

    cudaMemsetAsync(p_cnt, 0, (size_t)G * sizeof(int), 0);

    // prep all 4 conv weights (transpose + bf16 hi/lo split)
    wprep_kernel<<<256, 256>>>(c1w1, c1w2, c2w1, c2w2);

    // atom encoder (+ per-graph counts)
    atom_encode_kernel<<<(N * 32 + 255) / 256, 256>>>(x_feat, batch, atom_emb, p_x0, N);

    const int edge_blocks = (E * 32 + 255) / 256;
    const int gtc = (N + 127) / 128;

    // ---- conv1 ----
    cudaMemsetAsync(p_agg, 0, (size_t)N * ND * sizeof(float), 0);
    edge_msg_kernel<<<edge_blocks, 256>>>(edge_index, eaf, bond_emb, p_x0, p_agg, E);
    gemm_mma_kernel<true, true><<<gtc, 256, TCSM>>>(p_x0, p_agg, p_wp + 0 * 4096, c1b1, p_h, N);
    gemm_mma_kernel<false, false><<<gtc, 256, TCSM>>>(p_h, (const float*)nullptr,
                                                      p_wp + 1 * 4096, c1b2, p_x1, N);

    // ---- conv2 ----
    cudaMemsetAsync(p_agg, 0, (size_t)N * ND * sizeof(float), 0);
    edge_msg_kernel<<<edge_blocks, 256>>>(edge_index, eaf, bond_emb, p_x1, p_agg, E);
    gemm_mma_kernel<true, true><<<gtc, 256, TCSM>>>(p_x1, p_agg, p_wp + 2 * 4096, c2b1, p_h, N);
    gemm_mma_kernel<false, false><<<gtc, 256, TCSM>>>(p_h, (const float*)nullptr,
                                                      p_wp + 3 * 4096, c2b2, p_x2, N);

    // ---- pool + concat ----
    cudaMemsetAsync(p_pool, 0, (size_t)G * ND * sizeof(float), 0);
    pool_sum_kernel<<<(N * 32 + 255) / 256, 256>>>(p_x2, batch, p_pool, N);
    {
        int total = G * KMLP1;
        concat_kernel<<<(total + 255) / 256, 256>>>(p_pool, rdkit, p_min, G);
    }

    // ---- MLP (fp32 SIMT; small) ----
    gemm_kernel<64, 64, 8, 4, 8, true, 1><<<dim3(G / 64, H1 / 64), 128>>>(
        p_min, (const float*)nullptr, mw1, mb1, p_m1, G, KMLP1, H1);
    gemm_kernel<64, 64, 8, 4, 8, true, 1><<<dim3(G / 64, H2 / 64), 128>>>(
        p_m1, (const float*)nullptr, mw2, mb2, p_m2, G, H1, H2);
    final_dot_kernel<<<(G * 32 + 255) / 256, 256>>>(p_m2, mw3, mb3, out, G);

    (void)n_in; (void)out_size;
}

// round 5
// speedup vs baseline: 2.1821x; 1.2231x over previous
#include <cuda_runtime.h>
#include <cuda_bf16.h>
#include <cstdint>

// Problem constants (fixed by the dataset)
#define ND 128
#define NMAX 50000
#define EMAX 640000
#define GMAX 1024
#define RDM 200
#define H1 512
#define H2 256
#define KMLP1 (ND + RDM)   // 328

// ---------------- scratch (device globals; no allocation allowed) ----------
__device__ float g_x0[NMAX * ND];
__device__ float g_agg[NMAX * ND];
__device__ float g_h[NMAX * ND];
__device__ float g_x1[NMAX * ND];
__device__ float g_x2[NMAX * ND];
__device__ float g_pool[GMAX * ND];
__device__ int   g_cnt[GMAX];
__device__ float g_min[GMAX * KMLP1];
__device__ float g_m1[GMAX * H1];
__device__ float g_m2[GMAX * H2];
// prepped conv weights: per matrix 64KB = Wt hi (32KB) + Wt lo (32KB), [n][k] bf16
__device__ uint4 g_wp[4][4096];
// CSR sort scratch
__device__ int g_deg[NMAX];
__device__ int g_off[NMAX + 1];
__device__ int g_pos[NMAX];
__device__ int g_part[64];
__device__ int g_emeta[EMAX];    // packed per-edge meta (src | f0<<16 | f1<<20 | f2<<24)
__device__ int g_smeta[EMAX];    // meta in dst-sorted order

// ---------------- helpers ----------------------------------------------------
__device__ __forceinline__ unsigned long long pack2(float x, float y) {
    unsigned long long r;
    asm("mov.b64 %0, {%1, %2};" : "=l"(r) : "f"(x), "f"(y));
    return r;
}
__device__ __forceinline__ void unpack2(unsigned long long v, float& x, float& y) {
    asm("mov.b64 {%0, %1}, %2;" : "=f"(x), "=f"(y) : "l"(v));
}
__device__ __forceinline__ void ffma2(unsigned long long& d, unsigned long long a,
                                      unsigned long long b) {
    asm("fma.rn.f32x2 %0, %1, %2, %0;" : "+l"(d) : "l"(a), "l"(b));
}
__device__ __forceinline__ void red_add_v4(float* p, float a, float b, float c, float d) {
    asm volatile("red.global.add.v4.f32 [%0], {%1, %2, %3, %4};"
                 :: "l"(p), "f"(a), "f"(b), "f"(c), "f"(d) : "memory");
}
// hi/lo bf16x2 split of two floats (a=elem0/low half, b=elem1/high half)
__device__ __forceinline__ uint32_t hilo(float a, float b, uint32_t& lopack) {
    uint32_t h;
    asm("cvt.rn.bf16x2.f32 %0, %1, %2;" : "=r"(h) : "f"(b), "f"(a));
    float fa = __uint_as_float(h << 16);
    float fb = __uint_as_float(h & 0xffff0000u);
    float ra = a - fa, rb = b - fb;
    uint32_t l;
    asm("cvt.rn.bf16x2.f32 %0, %1, %2;" : "=r"(l) : "f"(rb), "f"(ra));
    lopack = l;
    return h;
}
// warp-level bf16 tensor-core mma (baseline PTX, works on plain sm_103)
__device__ __forceinline__ void mma16816(float* c, const uint32_t* a, const uint32_t* b) {
    asm volatile(
        "mma.sync.aligned.m16n8k16.row.col.f32.bf16.bf16.f32 "
        "{%0,%1,%2,%3}, {%4,%5,%6,%7}, {%8,%9}, {%0,%1,%2,%3};"
        : "+f"(c[0]), "+f"(c[1]), "+f"(c[2]), "+f"(c[3])
        : "r"(a[0]), "r"(a[1]), "r"(a[2]), "r"(a[3]), "r"(b[0]), "r"(b[1]));
}

// ---------------- CSR sort kernels -------------------------------------------
// pack meta + histogram of dst degrees
__global__ void edge_prep_kernel(const int* __restrict__ ei,
                                 const int* __restrict__ eaf, int E) {
    int e = blockIdx.x * blockDim.x + threadIdx.x;
    if (e >= E) return;
    int src = ei[e];
    int dst = ei[E + e];
    int f0 = eaf[e * 3 + 0], f1 = eaf[e * 3 + 1], f2 = eaf[e * 3 + 2];
    g_emeta[e] = src | (f0 << 16) | (f1 << 20) | (f2 << 24);
    atomicAdd(&g_deg[dst], 1);
}
// block-level exclusive scan (1024/block)
__global__ void scan1_kernel(int N) {
    __shared__ int sm[1024];
    int i = blockIdx.x * 1024 + threadIdx.x;
    int v = (i < N) ? g_deg[i] : 0;
    sm[threadIdx.x] = v;
    __syncthreads();
#pragma unroll
    for (int ofs = 1; ofs < 1024; ofs <<= 1) {
        int t = (threadIdx.x >= ofs) ? sm[threadIdx.x - ofs] : 0;
        __syncthreads();
        sm[threadIdx.x] += t;
        __syncthreads();
    }
    if (i < N) g_off[i] = sm[threadIdx.x] - v;   // exclusive
    if (threadIdx.x == 1023) g_part[blockIdx.x] = sm[1023];
}
__global__ void scan2_kernel(int nb) {
    if (threadIdx.x == 0) {
        int acc = 0;
        for (int i = 0; i < nb; i++) { int t = g_part[i]; g_part[i] = acc; acc += t; }
    }
}
__global__ void scan3_kernel(int N, int E) {
    int i = blockIdx.x * 1024 + threadIdx.x;
    if (i < N) {
        int v = g_off[i] + g_part[blockIdx.x];
        g_off[i] = v;
        g_pos[i] = v;
    }
    if (i == 0) g_off[N] = E;
}
// scatter meta into dst-sorted order
__global__ void scatter_kernel(const int* __restrict__ ei, int E) {
    int e = blockIdx.x * blockDim.x + threadIdx.x;
    if (e >= E) return;
    int dst = ei[E + e];
    int p = atomicAdd(&g_pos[dst], 1);
    g_smeta[p] = g_emeta[e];
}

// ---------------- gather-aggregate: out[n] = x[n] + sum relu(x[src]+bond) ----
__global__ void __launch_bounds__(256)
agg_gather_kernel(const float* __restrict__ xin, const float* __restrict__ bemb,
                  float* __restrict__ out, int N) {
    __shared__ int s_meta[8][32];
    int wid = threadIdx.x >> 5, lane = threadIdx.x & 31;
    int n = blockIdx.x * 8 + wid;
    if (n >= N) return;
    int s = g_off[n], e_end = g_off[n + 1];
    float4 acc = reinterpret_cast<const float4*>(xin + (size_t)n * ND)[lane];
    for (int base = s; base < e_end; base += 32) {
        int cnt = min(32, e_end - base);
        if (lane < cnt) s_meta[wid][lane] = g_smeta[base + lane];
        __syncwarp();
        for (int i = 0; i < cnt; i++) {
            int m = s_meta[wid][i];
            int src = m & 0xFFFF;
            float4 xs = reinterpret_cast<const float4*>(xin + (size_t)src * ND)[lane];
            float4 b0 = reinterpret_cast<const float4*>(bemb + ((m >> 16) & 15) * ND)[lane];
            float4 b1 = reinterpret_cast<const float4*>(bemb + (16 + ((m >> 20) & 15)) * ND)[lane];
            float4 b2 = reinterpret_cast<const float4*>(bemb + (32 + ((m >> 24) & 15)) * ND)[lane];
            acc.x += fmaxf(xs.x + b0.x + b1.x + b2.x, 0.f);
            acc.y += fmaxf(xs.y + b0.y + b1.y + b2.y, 0.f);
            acc.z += fmaxf(xs.z + b0.z + b1.z + b2.z, 0.f);
            acc.w += fmaxf(xs.w + b0.w + b1.w + b2.w, 0.f);
        }
        __syncwarp();
    }
    reinterpret_cast<float4*>(out + (size_t)n * ND)[lane] = acc;
}

// ---------------- kernel: W prep (transpose + hi/lo bf16 split) -------------
__global__ void wprep_kernel(const float* __restrict__ w0, const float* __restrict__ w1,
                             const float* __restrict__ w2, const float* __restrict__ w3) {
    int widx = blockIdx.x >> 6;
    int idx = (blockIdx.x & 63) * 256 + threadIdx.x;   // 0..16383
    const float* W = (widx == 0) ? w0 : (widx == 1) ? w1 : (widx == 2) ? w2 : w3;
    int n = idx >> 7, k = idx & 127;
    float w = W[k * 128 + n];
    __nv_bfloat16 h = __float2bfloat16(w);
    float r = w - __bfloat162float(h);
    __nv_bfloat16 l = __float2bfloat16(r);
    char* base = (char*)&g_wp[widx][0];
    uint32_t off = (uint32_t)(n * 128 + k) * 2u;
    *(__nv_bfloat16*)(base + off) = h;
    *(__nv_bfloat16*)(base + 32768 + off) = l;
}

// ---------------- kernel: tensor-core conv GEMM ------------------------------
// C[M,128] = act(A @ W + bias), bf16x3 split, fp32 accumulate.
#define SAK 136   // padded bf16 stride
#define TCSM (4 * 128 * SAK * 2)   // 139264 B

template <bool RELU>
__global__ void __launch_bounds__(256, 1)
gemm_mma_kernel(const float* __restrict__ A,
                const uint4* __restrict__ Wp, const float* __restrict__ bias,
                float* __restrict__ C, int M) {
    extern __shared__ char dsm[];
    __shared__ float s_bias[128];

    char* pAhi = dsm;
    char* pAlo = dsm + 128 * SAK * 2;
    char* pWhi = dsm + 2 * 128 * SAK * 2;
    char* pWlo = dsm + 3 * 128 * SAK * 2;
    const uint32_t* sAhi = (const uint32_t*)pAhi;
    const uint32_t* sAlo = (const uint32_t*)pAlo;
    const uint32_t* sWhi = (const uint32_t*)pWhi;
    const uint32_t* sWlo = (const uint32_t*)pWlo;

    const int tid = threadIdx.x, wid = tid >> 5, lane = tid & 31;
    const int g = lane >> 2, q = lane & 3;
    const int wm = wid & 3, wn = wid >> 2;
    const int brow = blockIdx.x * 128;

    if (tid < 128) s_bias[tid] = bias[tid];

    // ---- stage W ----
    {
#pragma unroll
        for (int i = 0; i < 8; i++) {
            int u = tid + i * 256;
            int n = u >> 4, kc = (u & 15);
            uint4 vh = Wp[u];
            uint4 vl = Wp[u + 2048];
            *(uint4*)(pWhi + n * (SAK * 2) + kc * 16) = vh;
            *(uint4*)(pWlo + n * (SAK * 2) + kc * 16) = vl;
        }
    }

    // ---- stage A: fp32 -> hi/lo bf16 ----
    {
        int row = tid >> 1;
        int c0 = (tid & 1) * 64;
        bool valid = (brow + row) < M;
        const float4* a4 = (const float4*)(A + (size_t)(brow + row) * 128 + c0);
        char* dAh = pAhi + row * (SAK * 2) + c0 * 2;
        char* dAl = pAlo + row * (SAK * 2) + c0 * 2;
#pragma unroll
        for (int i = 0; i < 8; i++) {
            float4 v0 = make_float4(0.f, 0.f, 0.f, 0.f), v1 = v0;
            if (valid) { v0 = a4[i * 2]; v1 = a4[i * 2 + 1]; }
            uint4 h, l;
            h.x = hilo(v0.x, v0.y, l.x);
            h.y = hilo(v0.z, v0.w, l.y);
            h.z = hilo(v1.x, v1.y, l.z);
            h.w = hilo(v1.z, v1.w, l.w);
            *(uint4*)(dAh + i * 16) = h;
            *(uint4*)(dAl + i * 16) = l;
        }
    }
    __syncthreads();

    // ---- main loop ----
    float acc[2][8][4];
#pragma unroll
    for (int mt = 0; mt < 2; mt++)
#pragma unroll
        for (int nt = 0; nt < 8; nt++)
#pragma unroll
            for (int j = 0; j < 4; j++) acc[mt][nt][j] = 0.f;

    const int ra0 = wm * 32 + g;
    const int nb0 = wn * 64 + g;

#pragma unroll
    for (int ks = 0; ks < 8; ks++) {
        const int k0 = ks * 16 + q * 2;
        uint32_t ah[2][4], al[2][4];
#pragma unroll
        for (int mt = 0; mt < 2; mt++) {
            int r = ra0 + mt * 16;
            int i00 = (r * SAK + k0) >> 1;
            int i10 = ((r + 8) * SAK + k0) >> 1;
            ah[mt][0] = sAhi[i00];     ah[mt][1] = sAhi[i10];
            ah[mt][2] = sAhi[i00 + 4]; ah[mt][3] = sAhi[i10 + 4];
            al[mt][0] = sAlo[i00];     al[mt][1] = sAlo[i10];
            al[mt][2] = sAlo[i00 + 4]; al[mt][3] = sAlo[i10 + 4];
        }
#pragma unroll
        for (int nt = 0; nt < 8; nt++) {
            int n = nb0 + nt * 8;
            int ib = (n * SAK + k0) >> 1;
            uint32_t bh[2], bl[2];
            bh[0] = sWhi[ib]; bh[1] = sWhi[ib + 4];
            bl[0] = sWlo[ib]; bl[1] = sWlo[ib + 4];
#pragma unroll
            for (int mt = 0; mt < 2; mt++) {
                mma16816(acc[mt][nt], ah[mt], bh);
                mma16816(acc[mt][nt], al[mt], bh);
                mma16816(acc[mt][nt], ah[mt], bl);
            }
        }
    }

    // ---- epilogue ----
#pragma unroll
    for (int mt = 0; mt < 2; mt++) {
        int r0 = brow + wm * 32 + mt * 16 + g;
#pragma unroll
        for (int nt = 0; nt < 8; nt++) {
            int col = wn * 64 + nt * 8 + q * 2;
            float bx = s_bias[col], by = s_bias[col + 1];
            float x0 = acc[mt][nt][0] + bx, y0 = acc[mt][nt][1] + by;
            float x1 = acc[mt][nt][2] + bx, y1 = acc[mt][nt][3] + by;
            if (RELU) {
                x0 = fmaxf(x0, 0.f); y0 = fmaxf(y0, 0.f);
                x1 = fmaxf(x1, 0.f); y1 = fmaxf(y1, 0.f);
            }
            if (r0 < M) {
                float2 o; o.x = x0; o.y = y0;
                *(float2*)(C + (size_t)r0 * 128 + col) = o;
            }
            if (r0 + 8 < M) {
                float2 o; o.x = x1; o.y = y1;
                *(float2*)(C + (size_t)(r0 + 8) * 128 + col) = o;
            }
        }
    }
}

// ---------------- kernel: atom encoder + graph-size histogram ---------------
__global__ void atom_encode_kernel(const int* __restrict__ xf,
                                   const int* __restrict__ batch,
                                   const float* __restrict__ aemb,
                                   float* __restrict__ xout, int N) {
    int warp = (blockIdx.x * blockDim.x + threadIdx.x) >> 5;
    int lane = threadIdx.x & 31;
    if (warp >= N) return;
    int n = warp;
    float4 acc = make_float4(0.f, 0.f, 0.f, 0.f);
#pragma unroll
    for (int f = 0; f < 9; f++) {
        int id = xf[n * 9 + f];
        const float4* row = reinterpret_cast<const float4*>(aemb + ((f << 6) + id) * ND);
        float4 v = row[lane];
        acc.x += v.x; acc.y += v.y; acc.z += v.z; acc.w += v.w;
    }
    reinterpret_cast<float4*>(xout + (size_t)n * ND)[lane] = acc;
    if (lane == 0) atomicAdd(&g_cnt[batch[n]], 1);
}

// ---------------- fp32 GEMM (MLP only) --------------------------------------
template <int BM, int BN, int BK, int TM, int TN, bool RELU, int MINB>
__global__ void __launch_bounds__((BM / TM) * (BN / TN), MINB)
gemm_kernel(const float* __restrict__ A,
            const float* __restrict__ W, const float* __restrict__ bias,
            float* __restrict__ C, int M, int K, int Nc) {
    constexpr int THREADS = (BM / TM) * (BN / TN);
    __shared__ float sA[BK][BM + 4];
    __shared__ float sW[BK][BN];

    const int tid = threadIdx.x;
    const int tn = tid % (BN / TN);
    const int tm = tid / (BN / TN);
    const int row0 = tm * TM;
    const int col0 = tn * TN;
    const int brow = blockIdx.x * BM;
    const int bcol = blockIdx.y * BN;

    unsigned long long acc[TM][TN / 2];
#pragma unroll
    for (int i = 0; i < TM; i++)
#pragma unroll
        for (int j = 0; j < TN / 2; j++) acc[i][j] = 0ull;

    for (int k0 = 0; k0 < K; k0 += BK) {
        constexpr int A_LOADS = (BM * BK / 4) / THREADS;
#pragma unroll
        for (int i = 0; i < A_LOADS; i++) {
            int idx = tid + i * THREADS;
            int m = idx / (BK / 4);
            int kq = idx % (BK / 4);
            int grow = brow + m;
            float4 v = make_float4(0.f, 0.f, 0.f, 0.f);
            if (grow < M)
                v = *reinterpret_cast<const float4*>(A + (size_t)grow * K + k0 + kq * 4);
            sA[kq * 4 + 0][m] = v.x;
            sA[kq * 4 + 1][m] = v.y;
            sA[kq * 4 + 2][m] = v.z;
            sA[kq * 4 + 3][m] = v.w;
        }
        constexpr int W_LOADS = (BK * BN / 4) / THREADS;
#pragma unroll
        for (int i = 0; i < W_LOADS; i++) {
            int idx = tid + i * THREADS;
            int kk = idx / (BN / 4);
            int cq = idx % (BN / 4);
            *reinterpret_cast<float4*>(&sW[kk][cq * 4]) =
                *reinterpret_cast<const float4*>(W + (size_t)(k0 + kk) * Nc + bcol + cq * 4);
        }
        __syncthreads();

#pragma unroll
        for (int kk = 0; kk < BK; kk++) {
            float a[TM];
#pragma unroll
            for (int i = 0; i < TM; i += 4) {
                float4 t = *reinterpret_cast<const float4*>(&sA[kk][row0 + i]);
                a[i] = t.x; a[i + 1] = t.y; a[i + 2] = t.z; a[i + 3] = t.w;
            }
            unsigned long long wv[TN / 2];
#pragma unroll
            for (int j = 0; j < TN; j += 4) {
                float4 t = *reinterpret_cast<const float4*>(&sW[kk][col0 + j]);
                wv[j / 2] = pack2(t.x, t.y);
                wv[j / 2 + 1] = pack2(t.z, t.w);
            }
#pragma unroll
            for (int i = 0; i < TM; i++) {
                unsigned long long ad = pack2(a[i], a[i]);
#pragma unroll
                for (int j = 0; j < TN / 2; j++) ffma2(acc[i][j], ad, wv[j]);
            }
        }
        __syncthreads();
    }

    float2 bv[TN / 2];
#pragma unroll
    for (int j = 0; j < TN / 2; j++)
        bv[j] = *reinterpret_cast<const float2*>(bias + bcol + col0 + 2 * j);
#pragma unroll
    for (int i = 0; i < TM; i++) {
        int grow = brow + row0 + i;
        if (grow >= M) continue;
#pragma unroll
        for (int j = 0; j < TN / 2; j++) {
            float x, y;
            unpack2(acc[i][j], x, y);
            x += bv[j].x; y += bv[j].y;
            if (RELU) { x = fmaxf(x, 0.f); y = fmaxf(y, 0.f); }
            float2 o; o.x = x; o.y = y;
            *reinterpret_cast<float2*>(C + (size_t)grow * Nc + bcol + col0 + 2 * j) = o;
        }
    }
}

// ---------------- pooling: sum per graph -------------------------------------
__global__ void pool_sum_kernel(const float* __restrict__ x,
                                const int* __restrict__ batch,
                                float* __restrict__ pool, int N) {
    int warp = (blockIdx.x * blockDim.x + threadIdx.x) >> 5;
    int lane = threadIdx.x & 31;
    if (warp >= N) return;
    int n = warp;
    int g = batch[n];
    float4 v = reinterpret_cast<const float4*>(x + (size_t)n * ND)[lane];
    float* p = pool + (size_t)g * ND + lane * 4;
    red_add_v4(p, v.x, v.y, v.z, v.w);
}

// ---------------- concat: pooled mean + rdkit --------------------------------
__global__ void concat_kernel(const float* __restrict__ pool,
                              const float* __restrict__ rdkit,
                              float* __restrict__ out, int G) {
    int idx = blockIdx.x * blockDim.x + threadIdx.x;
    int total = G * KMLP1;
    if (idx >= total) return;
    int g = idx / KMLP1;
    int c = idx - g * KMLP1;
    float v;
    if (c < ND) {
        float cnt = (float)max(g_cnt[g], 1);
        v = pool[g * ND + c] / cnt;
    } else {
        v = rdkit[(size_t)g * RDM + (c - ND)];
    }
    out[idx] = v;
}

// ---------------- final layer: [G,256] @ [256,1] -----------------------------
__global__ void final_dot_kernel(const float* __restrict__ m2,
                                 const float* __restrict__ w3,
                                 const float* __restrict__ b3,
                                 float* __restrict__ out, int G) {
    int warp = (blockIdx.x * blockDim.x + threadIdx.x) >> 5;
    int lane = threadIdx.x & 31;
    if (warp >= G) return;
    int g = warp;
    float s = 0.f;
#pragma unroll
    for (int c = lane; c < H2; c += 32) s += m2[(size_t)g * H2 + c] * w3[c];
#pragma unroll
    for (int off = 16; off > 0; off >>= 1) s += __shfl_xor_sync(0xFFFFFFFFu, s, off);
    if (lane == 0) out[g] = s + b3[0];
}

// ---------------- launch ------------------------------------------------------
extern "C" void kernel_launch(void* const* d_in, const int* in_sizes, int n_in,
                              void* d_out, int out_size) {
    const int* x_feat     = (const int*)d_in[0];
    const int* edge_index = (const int*)d_in[1];
    const int* eaf        = (const int*)d_in[2];
    const int* batch      = (const int*)d_in[3];
    const float* rdkit    = (const float*)d_in[4];
    const float* atom_emb = (const float*)d_in[5];
    const float* bond_emb = (const float*)d_in[6];
    const float* c1w1 = (const float*)d_in[7];
    const float* c1b1 = (const float*)d_in[8];
    const float* c1w2 = (const float*)d_in[9];
    const float* c1b2 = (const float*)d_in[10];
    const float* c2w1 = (const float*)d_in[11];
    const float* c2b1 = (const float*)d_in[12];
    const float* c2w2 = (const float*)d_in[13];
    const float* c2b2 = (const float*)d_in[14];
    const float* mw1 = (const float*)d_in[15];
    const float* mb1 = (const float*)d_in[16];
    const float* mw2 = (const float*)d_in[17];
    const float* mb2 = (const float*)d_in[18];
    const float* mw3 = (const float*)d_in[19];
    const float* mb3 = (const float*)d_in[20];
    float* out = (float*)d_out;

    const int N = in_sizes[0] / 9;
    const int E = in_sizes[1] / 2;
    const int G = in_sizes[4] / RDM;

    float *p_x0, *p_agg, *p_h, *p_x1, *p_x2, *p_pool, *p_min, *p_m1, *p_m2;
    int *p_cnt, *p_deg;
    uint4* p_wp;
    cudaGetSymbolAddress((void**)&p_x0, g_x0);
    cudaGetSymbolAddress((void**)&p_agg, g_agg);
    cudaGetSymbolAddress((void**)&p_h, g_h);
    cudaGetSymbolAddress((void**)&p_x1, g_x1);
    cudaGetSymbolAddress((void**)&p_x2, g_x2);
    cudaGetSymbolAddress((void**)&p_pool, g_pool);
    cudaGetSymbolAddress((void**)&p_cnt, g_cnt);
    cudaGetSymbolAddress((void**)&p_deg, g_deg);
    cudaGetSymbolAddress((void**)&p_min, g_min);
    cudaGetSymbolAddress((void**)&p_m1, g_m1);
    cudaGetSymbolAddress((void**)&p_m2, g_m2);
    cudaGetSymbolAddress((void**)&p_wp, g_wp);

    cudaFuncSetAttribute(gemm_mma_kernel<true>,
                         cudaFuncAttributeMaxDynamicSharedMemorySize, TCSM);
    cudaFuncSetAttribute(gemm_mma_kernel<false>,
                         cudaFuncAttributeMaxDynamicSharedMemorySize, TCSM);

    cudaMemsetAsync(p_cnt, 0, (size_t)G * sizeof(int), 0);
    cudaMemsetAsync(p_deg, 0, (size_t)N * sizeof(int), 0);

    // ---- CSR build (once; serves both convs) ----
    const int scan_blocks = (N + 1023) / 1024;
    edge_prep_kernel<<<(E + 255) / 256, 256>>>(edge_index, eaf, E);
    scan1_kernel<<<scan_blocks, 1024>>>(N);
    scan2_kernel<<<1, 32>>>(scan_blocks);
    scan3_kernel<<<scan_blocks, 1024>>>(N, E);
    scatter_kernel<<<(E + 255) / 256, 256>>>(edge_index, E);

    // prep all 4 conv weights + atom encoder
    wprep_kernel<<<256, 256>>>(c1w1, c1w2, c2w1, c2w2);
    atom_encode_kernel<<<(N * 32 + 255) / 256, 256>>>(x_feat, batch, atom_emb, p_x0, N);

    const int agg_blocks = (N + 7) / 8;
    const int gtc = (N + 127) / 128;

    // ---- conv1 ----
    agg_gather_kernel<<<agg_blocks, 256>>>(p_x0, bond_emb, p_agg, N);
    gemm_mma_kernel<true><<<gtc, 256, TCSM>>>(p_agg, p_wp + 0 * 4096, c1b1, p_h, N);
    gemm_mma_kernel<false><<<gtc, 256, TCSM>>>(p_h, p_wp + 1 * 4096, c1b2, p_x1, N);

    // ---- conv2 ----
    agg_gather_kernel<<<agg_blocks, 256>>>(p_x1, bond_emb, p_agg, N);
    gemm_mma_kernel<true><<<gtc, 256, TCSM>>>(p_agg, p_wp + 2 * 4096, c2b1, p_h, N);
    gemm_mma_kernel<false><<<gtc, 256, TCSM>>>(p_h, p_wp + 3 * 4096, c2b2, p_x2, N);

    // ---- pool + concat ----
    cudaMemsetAsync(p_pool, 0, (size_t)G * ND * sizeof(float), 0);
    pool_sum_kernel<<<(N * 32 + 255) / 256, 256>>>(p_x2, batch, p_pool, N);
    {
        int total = G * KMLP1;
        concat_kernel<<<(total + 255) / 256, 256>>>(p_pool, rdkit, p_min, G);
    }

    // ---- MLP (fp32 SIMT; small) ----
    gemm_kernel<64, 64, 8, 4, 8, true, 1><<<dim3(G / 64, H1 / 64), 128>>>(
        p_min, mw1, mb1, p_m1, G, KMLP1, H1);
    gemm_kernel<64, 64, 8, 4, 8, true, 1><<<dim3(G / 64, H2 / 64), 128>>>(
        p_m1, mw2, mb2, p_m2, G, H1, H2);
    final_dot_kernel<<<(G * 32 + 255) / 256, 256>>>(p_m2, mw3, mb3, out, G);

    (void)n_in; (void)out_size;
}

// round 6
// speedup vs baseline: 2.3114x; 1.0593x over previous
#include <cuda_runtime.h>
#include <cuda_bf16.h>
#include <cstdint>

// Problem constants (fixed by the dataset)
#define ND 128
#define NMAX 50000
#define EMAX 640000
#define GMAX 1024
#define RDM 200
#define H1 512
#define H2 256
#define KMLP1 (ND + RDM)   // 328

// ---------------- scratch (device globals; no allocation allowed) ----------
__device__ float g_x0[NMAX * ND];
__device__ float g_agg[NMAX * ND];
__device__ float g_x1[NMAX * ND];
__device__ float g_x2[NMAX * ND];
__device__ float g_pool[GMAX * ND];
__device__ int   g_cnt[GMAX];
__device__ float g_min[GMAX * KMLP1];
__device__ float g_m1[GMAX * H1];
__device__ float g_m2[GMAX * H2];
// prepped conv weights: per matrix 64KB = Wt hi (32KB) + Wt lo (32KB), [n][k] bf16
__device__ uint4 g_wp[4][4096];
// CSR sort scratch
__device__ int g_deg[NMAX];
__device__ int g_off[NMAX + 1];
__device__ int g_pos[NMAX];
__device__ int g_part[64];
__device__ int g_emeta[EMAX];    // packed per-edge meta (src | f0<<16 | f1<<20 | f2<<24)
__device__ int g_smeta[EMAX];    // meta in dst-sorted order

// ---------------- helpers ----------------------------------------------------
__device__ __forceinline__ unsigned long long pack2(float x, float y) {
    unsigned long long r;
    asm("mov.b64 %0, {%1, %2};" : "=l"(r) : "f"(x), "f"(y));
    return r;
}
__device__ __forceinline__ void unpack2(unsigned long long v, float& x, float& y) {
    asm("mov.b64 {%0, %1}, %2;" : "=f"(x), "=f"(y) : "l"(v));
}
__device__ __forceinline__ void ffma2(unsigned long long& d, unsigned long long a,
                                      unsigned long long b) {
    asm("fma.rn.f32x2 %0, %1, %2, %0;" : "+l"(d) : "l"(a), "l"(b));
}
__device__ __forceinline__ void red_add_v4(float* p, float a, float b, float c, float d) {
    asm volatile("red.global.add.v4.f32 [%0], {%1, %2, %3, %4};"
                 :: "l"(p), "f"(a), "f"(b), "f"(c), "f"(d) : "memory");
}
// hi/lo bf16x2 split of two floats (a=elem0/low half, b=elem1/high half)
__device__ __forceinline__ uint32_t hilo(float a, float b, uint32_t& lopack) {
    uint32_t h;
    asm("cvt.rn.bf16x2.f32 %0, %1, %2;" : "=r"(h) : "f"(b), "f"(a));
    float fa = __uint_as_float(h << 16);
    float fb = __uint_as_float(h & 0xffff0000u);
    float ra = a - fa, rb = b - fb;
    uint32_t l;
    asm("cvt.rn.bf16x2.f32 %0, %1, %2;" : "=r"(l) : "f"(rb), "f"(ra));
    lopack = l;
    return h;
}
// warp-level bf16 tensor-core mma (baseline PTX, works on plain sm_103)
__device__ __forceinline__ void mma16816(float* c, const uint32_t* a, const uint32_t* b) {
    asm volatile(
        "mma.sync.aligned.m16n8k16.row.col.f32.bf16.bf16.f32 "
        "{%0,%1,%2,%3}, {%4,%5,%6,%7}, {%8,%9}, {%0,%1,%2,%3};"
        : "+f"(c[0]), "+f"(c[1]), "+f"(c[2]), "+f"(c[3])
        : "r"(a[0]), "r"(a[1]), "r"(a[2]), "r"(a[3]), "r"(b[0]), "r"(b[1]));
}

// ---------------- CSR sort kernels -------------------------------------------
__global__ void edge_prep_kernel(const int* __restrict__ ei,
                                 const int* __restrict__ eaf, int E) {
    int e = blockIdx.x * blockDim.x + threadIdx.x;
    if (e >= E) return;
    int src = ei[e];
    int dst = ei[E + e];
    int f0 = eaf[e * 3 + 0], f1 = eaf[e * 3 + 1], f2 = eaf[e * 3 + 2];
    g_emeta[e] = src | (f0 << 16) | (f1 << 20) | (f2 << 24);
    atomicAdd(&g_deg[dst], 1);
}
__global__ void scan1_kernel(int N) {
    __shared__ int sm[1024];
    int i = blockIdx.x * 1024 + threadIdx.x;
    int v = (i < N) ? g_deg[i] : 0;
    sm[threadIdx.x] = v;
    __syncthreads();
#pragma unroll
    for (int ofs = 1; ofs < 1024; ofs <<= 1) {
        int t = (threadIdx.x >= ofs) ? sm[threadIdx.x - ofs] : 0;
        __syncthreads();
        sm[threadIdx.x] += t;
        __syncthreads();
    }
    if (i < N) g_off[i] = sm[threadIdx.x] - v;   // exclusive
    if (threadIdx.x == 1023) g_part[blockIdx.x] = sm[1023];
}
__global__ void scan2_kernel(int nb) {
    if (threadIdx.x == 0) {
        int acc = 0;
        for (int i = 0; i < nb; i++) { int t = g_part[i]; g_part[i] = acc; acc += t; }
    }
}
__global__ void scan3_kernel(int N, int E) {
    int i = blockIdx.x * 1024 + threadIdx.x;
    if (i < N) {
        int v = g_off[i] + g_part[blockIdx.x];
        g_off[i] = v;
        g_pos[i] = v;
    }
    if (i == 0) g_off[N] = E;
}
__global__ void scatter_kernel(const int* __restrict__ ei, int E) {
    int e = blockIdx.x * blockDim.x + threadIdx.x;
    if (e >= E) return;
    int dst = ei[E + e];
    int p = atomicAdd(&g_pos[dst], 1);
    g_smeta[p] = g_emeta[e];
}

// ---------------- gather-aggregate: out[n] = x[n] + sum relu(x[src]+bond) ----
__global__ void __launch_bounds__(256)
agg_gather_kernel(const float* __restrict__ xin, const float* __restrict__ bemb,
                  float* __restrict__ out, int N) {
    __shared__ int s_meta[8][32];
    int wid = threadIdx.x >> 5, lane = threadIdx.x & 31;
    int n = blockIdx.x * 8 + wid;
    if (n >= N) return;
    int s = g_off[n], e_end = g_off[n + 1];
    float4 acc = reinterpret_cast<const float4*>(xin + (size_t)n * ND)[lane];
    for (int base = s; base < e_end; base += 32) {
        int cnt = min(32, e_end - base);
        if (lane < cnt) s_meta[wid][lane] = g_smeta[base + lane];
        __syncwarp();
        for (int i = 0; i < cnt; i++) {
            int m = s_meta[wid][i];
            int src = m & 0xFFFF;
            float4 xs = reinterpret_cast<const float4*>(xin + (size_t)src * ND)[lane];
            float4 b0 = reinterpret_cast<const float4*>(bemb + ((m >> 16) & 15) * ND)[lane];
            float4 b1 = reinterpret_cast<const float4*>(bemb + (16 + ((m >> 20) & 15)) * ND)[lane];
            float4 b2 = reinterpret_cast<const float4*>(bemb + (32 + ((m >> 24) & 15)) * ND)[lane];
            acc.x += fmaxf(xs.x + b0.x + b1.x + b2.x, 0.f);
            acc.y += fmaxf(xs.y + b0.y + b1.y + b2.y, 0.f);
            acc.z += fmaxf(xs.z + b0.z + b1.z + b2.z, 0.f);
            acc.w += fmaxf(xs.w + b0.w + b1.w + b2.w, 0.f);
        }
        __syncwarp();
    }
    reinterpret_cast<float4*>(out + (size_t)n * ND)[lane] = acc;
}

// ---------------- kernel: W prep (transpose + hi/lo bf16 split) -------------
__global__ void wprep_kernel(const float* __restrict__ w0, const float* __restrict__ w1,
                             const float* __restrict__ w2, const float* __restrict__ w3) {
    int widx = blockIdx.x >> 6;
    int idx = (blockIdx.x & 63) * 256 + threadIdx.x;   // 0..16383
    const float* W = (widx == 0) ? w0 : (widx == 1) ? w1 : (widx == 2) ? w2 : w3;
    int n = idx >> 7, k = idx & 127;
    float w = W[k * 128 + n];
    __nv_bfloat16 h = __float2bfloat16(w);
    float r = w - __bfloat162float(h);
    __nv_bfloat16 l = __float2bfloat16(r);
    char* base = (char*)&g_wp[widx][0];
    uint32_t off = (uint32_t)(n * 128 + k) * 2u;
    *(__nv_bfloat16*)(base + off) = h;
    *(__nv_bfloat16*)(base + 32768 + off) = l;
}

// ---------------- fused 2-layer tensor-core conv GEMM ------------------------
// C = relu(A @ W1 + b1) @ W2 + b2 for one 128-row tile; bf16x3 split; fp32 acc.
#define SAK 136   // padded bf16 stride
#define FSM (6 * 128 * SAK * 2)   // Ahi,Alo,W1hi,W1lo,W2hi,W2lo = 208896 B

__global__ void __launch_bounds__(256, 1)
gemm_fused_kernel(const float* __restrict__ A,
                  const uint4* __restrict__ Wp1, const uint4* __restrict__ Wp2,
                  const float* __restrict__ b1, const float* __restrict__ b2,
                  float* __restrict__ C, int M) {
    extern __shared__ char dsm[];
    __shared__ float s_b1[128];
    __shared__ float s_b2[128];

    char* pAhi  = dsm;
    char* pAlo  = dsm + 1 * 128 * SAK * 2;
    char* pW1hi = dsm + 2 * 128 * SAK * 2;
    char* pW1lo = dsm + 3 * 128 * SAK * 2;
    char* pW2hi = dsm + 4 * 128 * SAK * 2;
    char* pW2lo = dsm + 5 * 128 * SAK * 2;
    const uint32_t* sAhi = (const uint32_t*)pAhi;
    const uint32_t* sAlo = (const uint32_t*)pAlo;

    const int tid = threadIdx.x, wid = tid >> 5, lane = tid & 31;
    const int g = lane >> 2, q = lane & 3;
    const int wm = wid & 3, wn = wid >> 2;
    const int brow = blockIdx.x * 128;

    if (tid < 128) { s_b1[tid] = b1[tid]; s_b2[tid] = b2[tid]; }

    // ---- stage W1, W2 (hi + lo) ----
#pragma unroll
    for (int i = 0; i < 8; i++) {
        int u = tid + i * 256;              // 0..2047
        int n = u >> 4, kc = (u & 15);
        *(uint4*)(pW1hi + n * (SAK * 2) + kc * 16) = Wp1[u];
        *(uint4*)(pW1lo + n * (SAK * 2) + kc * 16) = Wp1[u + 2048];
        *(uint4*)(pW2hi + n * (SAK * 2) + kc * 16) = Wp2[u];
        *(uint4*)(pW2lo + n * (SAK * 2) + kc * 16) = Wp2[u + 2048];
    }

    // ---- stage A: fp32 -> hi/lo bf16 ----
    {
        int row = tid >> 1;
        int c0 = (tid & 1) * 64;
        bool valid = (brow + row) < M;
        const float4* a4 = (const float4*)(A + (size_t)(brow + row) * 128 + c0);
        char* dAh = pAhi + row * (SAK * 2) + c0 * 2;
        char* dAl = pAlo + row * (SAK * 2) + c0 * 2;
#pragma unroll
        for (int i = 0; i < 8; i++) {
            float4 v0 = make_float4(0.f, 0.f, 0.f, 0.f), v1 = v0;
            if (valid) { v0 = a4[i * 2]; v1 = a4[i * 2 + 1]; }
            uint4 h, l;
            h.x = hilo(v0.x, v0.y, l.x);
            h.y = hilo(v0.z, v0.w, l.y);
            h.z = hilo(v1.x, v1.y, l.z);
            h.w = hilo(v1.z, v1.w, l.w);
            *(uint4*)(dAh + i * 16) = h;
            *(uint4*)(dAl + i * 16) = l;
        }
    }
    __syncthreads();

    const int ra0 = wm * 32 + g;
    const int nb0 = wn * 64 + g;
    float acc[2][8][4];

    // ================= layer 1 =================
#pragma unroll
    for (int mt = 0; mt < 2; mt++)
#pragma unroll
        for (int nt = 0; nt < 8; nt++)
#pragma unroll
            for (int j = 0; j < 4; j++) acc[mt][nt][j] = 0.f;

    {
        const uint32_t* sWhi = (const uint32_t*)pW1hi;
        const uint32_t* sWlo = (const uint32_t*)pW1lo;
#pragma unroll
        for (int ks = 0; ks < 8; ks++) {
            const int k0 = ks * 16 + q * 2;
            uint32_t ah[2][4], al[2][4];
#pragma unroll
            for (int mt = 0; mt < 2; mt++) {
                int r = ra0 + mt * 16;
                int i00 = (r * SAK + k0) >> 1;
                int i10 = ((r + 8) * SAK + k0) >> 1;
                ah[mt][0] = sAhi[i00];     ah[mt][1] = sAhi[i10];
                ah[mt][2] = sAhi[i00 + 4]; ah[mt][3] = sAhi[i10 + 4];
                al[mt][0] = sAlo[i00];     al[mt][1] = sAlo[i10];
                al[mt][2] = sAlo[i00 + 4]; al[mt][3] = sAlo[i10 + 4];
            }
#pragma unroll
            for (int nt = 0; nt < 8; nt++) {
                int n = nb0 + nt * 8;
                int ib = (n * SAK + k0) >> 1;
                uint32_t bh[2], bl[2];
                bh[0] = sWhi[ib]; bh[1] = sWhi[ib + 4];
                bl[0] = sWlo[ib]; bl[1] = sWlo[ib + 4];
#pragma unroll
                for (int mt = 0; mt < 2; mt++) {
                    mma16816(acc[mt][nt], ah[mt], bh);
                    mma16816(acc[mt][nt], al[mt], bh);
                    mma16816(acc[mt][nt], ah[mt], bl);
                }
            }
        }
    }
    __syncthreads();   // everyone done reading A tiles before overwrite

    // ---- h = relu(acc + b1) -> hi/lo bf16 back into A buffers ----
#pragma unroll
    for (int mt = 0; mt < 2; mt++) {
        int r0 = wm * 32 + mt * 16 + g;
#pragma unroll
        for (int nt = 0; nt < 8; nt++) {
            int col = wn * 64 + nt * 8 + q * 2;
            float bx = s_b1[col], by = s_b1[col + 1];
            float x0 = fmaxf(acc[mt][nt][0] + bx, 0.f);
            float y0 = fmaxf(acc[mt][nt][1] + by, 0.f);
            float x1 = fmaxf(acc[mt][nt][2] + bx, 0.f);
            float y1 = fmaxf(acc[mt][nt][3] + by, 0.f);
            uint32_t l0, l1;
            uint32_t h0 = hilo(x0, y0, l0);
            uint32_t h1 = hilo(x1, y1, l1);
            uint32_t o0 = (uint32_t)(r0 * SAK + col) * 2u;
            uint32_t o1 = (uint32_t)((r0 + 8) * SAK + col) * 2u;
            *(uint32_t*)(pAhi + o0) = h0;
            *(uint32_t*)(pAlo + o0) = l0;
            *(uint32_t*)(pAhi + o1) = h1;
            *(uint32_t*)(pAlo + o1) = l1;
        }
    }
    __syncthreads();

    // ================= layer 2 =================
#pragma unroll
    for (int mt = 0; mt < 2; mt++)
#pragma unroll
        for (int nt = 0; nt < 8; nt++)
#pragma unroll
            for (int j = 0; j < 4; j++) acc[mt][nt][j] = 0.f;

    {
        const uint32_t* sWhi = (const uint32_t*)pW2hi;
        const uint32_t* sWlo = (const uint32_t*)pW2lo;
#pragma unroll
        for (int ks = 0; ks < 8; ks++) {
            const int k0 = ks * 16 + q * 2;
            uint32_t ah[2][4], al[2][4];
#pragma unroll
            for (int mt = 0; mt < 2; mt++) {
                int r = ra0 + mt * 16;
                int i00 = (r * SAK + k0) >> 1;
                int i10 = ((r + 8) * SAK + k0) >> 1;
                ah[mt][0] = sAhi[i00];     ah[mt][1] = sAhi[i10];
                ah[mt][2] = sAhi[i00 + 4]; ah[mt][3] = sAhi[i10 + 4];
                al[mt][0] = sAlo[i00];     al[mt][1] = sAlo[i10];
                al[mt][2] = sAlo[i00 + 4]; al[mt][3] = sAlo[i10 + 4];
            }
#pragma unroll
            for (int nt = 0; nt < 8; nt++) {
                int n = nb0 + nt * 8;
                int ib = (n * SAK + k0) >> 1;
                uint32_t bh[2], bl[2];
                bh[0] = sWhi[ib]; bh[1] = sWhi[ib + 4];
                bl[0] = sWlo[ib]; bl[1] = sWlo[ib + 4];
#pragma unroll
                for (int mt = 0; mt < 2; mt++) {
                    mma16816(acc[mt][nt], ah[mt], bh);
                    mma16816(acc[mt][nt], al[mt], bh);
                    mma16816(acc[mt][nt], ah[mt], bl);
                }
            }
        }
    }

    // ---- epilogue: C = acc + b2 ----
#pragma unroll
    for (int mt = 0; mt < 2; mt++) {
        int r0 = brow + wm * 32 + mt * 16 + g;
#pragma unroll
        for (int nt = 0; nt < 8; nt++) {
            int col = wn * 64 + nt * 8 + q * 2;
            float bx = s_b2[col], by = s_b2[col + 1];
            if (r0 < M) {
                float2 o; o.x = acc[mt][nt][0] + bx; o.y = acc[mt][nt][1] + by;
                *(float2*)(C + (size_t)r0 * 128 + col) = o;
            }
            if (r0 + 8 < M) {
                float2 o; o.x = acc[mt][nt][2] + bx; o.y = acc[mt][nt][3] + by;
                *(float2*)(C + (size_t)(r0 + 8) * 128 + col) = o;
            }
        }
    }
}

// ---------------- kernel: atom encoder + graph-size histogram ---------------
__global__ void atom_encode_kernel(const int* __restrict__ xf,
                                   const int* __restrict__ batch,
                                   const float* __restrict__ aemb,
                                   float* __restrict__ xout, int N) {
    int warp = (blockIdx.x * blockDim.x + threadIdx.x) >> 5;
    int lane = threadIdx.x & 31;
    if (warp >= N) return;
    int n = warp;
    float4 acc = make_float4(0.f, 0.f, 0.f, 0.f);
#pragma unroll
    for (int f = 0; f < 9; f++) {
        int id = xf[n * 9 + f];
        const float4* row = reinterpret_cast<const float4*>(aemb + ((f << 6) + id) * ND);
        float4 v = row[lane];
        acc.x += v.x; acc.y += v.y; acc.z += v.z; acc.w += v.w;
    }
    reinterpret_cast<float4*>(xout + (size_t)n * ND)[lane] = acc;
    if (lane == 0) atomicAdd(&g_cnt[batch[n]], 1);
}

// ---------------- fp32 GEMM (MLP only) --------------------------------------
template <int BM, int BN, int BK, int TM, int TN, bool RELU, int MINB>
__global__ void __launch_bounds__((BM / TM) * (BN / TN), MINB)
gemm_kernel(const float* __restrict__ A,
            const float* __restrict__ W, const float* __restrict__ bias,
            float* __restrict__ C, int M, int K, int Nc) {
    constexpr int THREADS = (BM / TM) * (BN / TN);
    __shared__ float sA[BK][BM + 4];
    __shared__ float sW[BK][BN];

    const int tid = threadIdx.x;
    const int tn = tid % (BN / TN);
    const int tm = tid / (BN / TN);
    const int row0 = tm * TM;
    const int col0 = tn * TN;
    const int brow = blockIdx.x * BM;
    const int bcol = blockIdx.y * BN;

    unsigned long long acc[TM][TN / 2];
#pragma unroll
    for (int i = 0; i < TM; i++)
#pragma unroll
        for (int j = 0; j < TN / 2; j++) acc[i][j] = 0ull;

    for (int k0 = 0; k0 < K; k0 += BK) {
        constexpr int A_LOADS = (BM * BK / 4) / THREADS;
#pragma unroll
        for (int i = 0; i < A_LOADS; i++) {
            int idx = tid + i * THREADS;
            int m = idx / (BK / 4);
            int kq = idx % (BK / 4);
            int grow = brow + m;
            float4 v = make_float4(0.f, 0.f, 0.f, 0.f);
            if (grow < M)
                v = *reinterpret_cast<const float4*>(A + (size_t)grow * K + k0 + kq * 4);
            sA[kq * 4 + 0][m] = v.x;
            sA[kq * 4 + 1][m] = v.y;
            sA[kq * 4 + 2][m] = v.z;
            sA[kq * 4 + 3][m] = v.w;
        }
        constexpr int W_LOADS = (BK * BN / 4) / THREADS;
#pragma unroll
        for (int i = 0; i < W_LOADS; i++) {
            int idx = tid + i * THREADS;
            int kk = idx / (BN / 4);
            int cq = idx % (BN / 4);
            *reinterpret_cast<float4*>(&sW[kk][cq * 4]) =
                *reinterpret_cast<const float4*>(W + (size_t)(k0 + kk) * Nc + bcol + cq * 4);
        }
        __syncthreads();

#pragma unroll
        for (int kk = 0; kk < BK; kk++) {
            float a[TM];
#pragma unroll
            for (int i = 0; i < TM; i += 4) {
                float4 t = *reinterpret_cast<const float4*>(&sA[kk][row0 + i]);
                a[i] = t.x; a[i + 1] = t.y; a[i + 2] = t.z; a[i + 3] = t.w;
            }
            unsigned long long wv[TN / 2];
#pragma unroll
            for (int j = 0; j < TN; j += 4) {
                float4 t = *reinterpret_cast<const float4*>(&sW[kk][col0 + j]);
                wv[j / 2] = pack2(t.x, t.y);
                wv[j / 2 + 1] = pack2(t.z, t.w);
            }
#pragma unroll
            for (int i = 0; i < TM; i++) {
                unsigned long long ad = pack2(a[i], a[i]);
#pragma unroll
                for (int j = 0; j < TN / 2; j++) ffma2(acc[i][j], ad, wv[j]);
            }
        }
        __syncthreads();
    }

    float2 bv[TN / 2];
#pragma unroll
    for (int j = 0; j < TN / 2; j++)
        bv[j] = *reinterpret_cast<const float2*>(bias + bcol + col0 + 2 * j);
#pragma unroll
    for (int i = 0; i < TM; i++) {
        int grow = brow + row0 + i;
        if (grow >= M) continue;
#pragma unroll
        for (int j = 0; j < TN / 2; j++) {
            float x, y;
            unpack2(acc[i][j], x, y);
            x += bv[j].x; y += bv[j].y;
            if (RELU) { x = fmaxf(x, 0.f); y = fmaxf(y, 0.f); }
            float2 o; o.x = x; o.y = y;
            *reinterpret_cast<float2*>(C + (size_t)grow * Nc + bcol + col0 + 2 * j) = o;
        }
    }
}

// ---------------- pooling: sum per graph -------------------------------------
__global__ void pool_sum_kernel(const float* __restrict__ x,
                                const int* __restrict__ batch,
                                float* __restrict__ pool, int N) {
    int warp = (blockIdx.x * blockDim.x + threadIdx.x) >> 5;
    int lane = threadIdx.x & 31;
    if (warp >= N) return;
    int n = warp;
    int g = batch[n];
    float4 v = reinterpret_cast<const float4*>(x + (size_t)n * ND)[lane];
    float* p = pool + (size_t)g * ND + lane * 4;
    red_add_v4(p, v.x, v.y, v.z, v.w);
}

// ---------------- concat: pooled mean + rdkit --------------------------------
__global__ void concat_kernel(const float* __restrict__ pool,
                              const float* __restrict__ rdkit,
                              float* __restrict__ out, int G) {
    int idx = blockIdx.x * blockDim.x + threadIdx.x;
    int total = G * KMLP1;
    if (idx >= total) return;
    int g = idx / KMLP1;
    int c = idx - g * KMLP1;
    float v;
    if (c < ND) {
        float cnt = (float)max(g_cnt[g], 1);
        v = pool[g * ND + c] / cnt;
    } else {
        v = rdkit[(size_t)g * RDM + (c - ND)];
    }
    out[idx] = v;
}

// ---------------- final layer: [G,256] @ [256,1] -----------------------------
__global__ void final_dot_kernel(const float* __restrict__ m2,
                                 const float* __restrict__ w3,
                                 const float* __restrict__ b3,
                                 float* __restrict__ out, int G) {
    int warp = (blockIdx.x * blockDim.x + threadIdx.x) >> 5;
    int lane = threadIdx.x & 31;
    if (warp >= G) return;
    int g = warp;
    float s = 0.f;
#pragma unroll
    for (int c = lane; c < H2; c += 32) s += m2[(size_t)g * H2 + c] * w3[c];
#pragma unroll
    for (int off = 16; off > 0; off >>= 1) s += __shfl_xor_sync(0xFFFFFFFFu, s, off);
    if (lane == 0) out[g] = s + b3[0];
}

// ---------------- launch ------------------------------------------------------
extern "C" void kernel_launch(void* const* d_in, const int* in_sizes, int n_in,
                              void* d_out, int out_size) {
    const int* x_feat     = (const int*)d_in[0];
    const int* edge_index = (const int*)d_in[1];
    const int* eaf        = (const int*)d_in[2];
    const int* batch      = (const int*)d_in[3];
    const float* rdkit    = (const float*)d_in[4];
    const float* atom_emb = (const float*)d_in[5];
    const float* bond_emb = (const float*)d_in[6];
    const float* c1w1 = (const float*)d_in[7];
    const float* c1b1 = (const float*)d_in[8];
    const float* c1w2 = (const float*)d_in[9];
    const float* c1b2 = (const float*)d_in[10];
    const float* c2w1 = (const float*)d_in[11];
    const float* c2b1 = (const float*)d_in[12];
    const float* c2w2 = (const float*)d_in[13];
    const float* c2b2 = (const float*)d_in[14];
    const float* mw1 = (const float*)d_in[15];
    const float* mb1 = (const float*)d_in[16];
    const float* mw2 = (const float*)d_in[17];
    const float* mb2 = (const float*)d_in[18];
    const float* mw3 = (const float*)d_in[19];
    const float* mb3 = (const float*)d_in[20];
    float* out = (float*)d_out;

    const int N = in_sizes[0] / 9;
    const int E = in_sizes[1] / 2;
    const int G = in_sizes[4] / RDM;

    float *p_x0, *p_agg, *p_x1, *p_x2, *p_pool, *p_min, *p_m1, *p_m2;
    int *p_cnt, *p_deg;
    uint4* p_wp;
    cudaGetSymbolAddress((void**)&p_x0, g_x0);
    cudaGetSymbolAddress((void**)&p_agg, g_agg);
    cudaGetSymbolAddress((void**)&p_x1, g_x1);
    cudaGetSymbolAddress((void**)&p_x2, g_x2);
    cudaGetSymbolAddress((void**)&p_pool, g_pool);
    cudaGetSymbolAddress((void**)&p_cnt, g_cnt);
    cudaGetSymbolAddress((void**)&p_deg, g_deg);
    cudaGetSymbolAddress((void**)&p_min, g_min);
    cudaGetSymbolAddress((void**)&p_m1, g_m1);
    cudaGetSymbolAddress((void**)&p_m2, g_m2);
    cudaGetSymbolAddress((void**)&p_wp, g_wp);

    cudaFuncSetAttribute(gemm_fused_kernel,
                         cudaFuncAttributeMaxDynamicSharedMemorySize, FSM);

    cudaMemsetAsync(p_cnt, 0, (size_t)G * sizeof(int), 0);
    cudaMemsetAsync(p_deg, 0, (size_t)N * sizeof(int), 0);

    // ---- CSR build (once; serves both convs) ----
    const int scan_blocks = (N + 1023) / 1024;
    edge_prep_kernel<<<(E + 255) / 256, 256>>>(edge_index, eaf, E);
    scan1_kernel<<<scan_blocks, 1024>>>(N);
    scan2_kernel<<<1, 32>>>(scan_blocks);
    scan3_kernel<<<scan_blocks, 1024>>>(N, E);
    scatter_kernel<<<(E + 255) / 256, 256>>>(edge_index, E);

    // prep all 4 conv weights + atom encoder
    wprep_kernel<<<256, 256>>>(c1w1, c1w2, c2w1, c2w2);
    atom_encode_kernel<<<(N * 32 + 255) / 256, 256>>>(x_feat, batch, atom_emb, p_x0, N);

    const int agg_blocks = (N + 7) / 8;
    const int gtc = (N + 127) / 128;

    // ---- conv1 (fused 2-layer GEMM) ----
    agg_gather_kernel<<<agg_blocks, 256>>>(p_x0, bond_emb, p_agg, N);
    gemm_fused_kernel<<<gtc, 256, FSM>>>(p_agg, p_wp + 0 * 4096, p_wp + 1 * 4096,
                                         c1b1, c1b2, p_x1, N);

    // ---- conv2 ----
    agg_gather_kernel<<<agg_blocks, 256>>>(p_x1, bond_emb, p_agg, N);
    gemm_fused_kernel<<<gtc, 256, FSM>>>(p_agg, p_wp + 2 * 4096, p_wp + 3 * 4096,
                                         c2b1, c2b2, p_x2, N);

    // ---- pool + concat ----
    cudaMemsetAsync(p_pool, 0, (size_t)G * ND * sizeof(float), 0);
    pool_sum_kernel<<<(N * 32 + 255) / 256, 256>>>(p_x2, batch, p_pool, N);
    {
        int total = G * KMLP1;
        concat_kernel<<<(total + 255) / 256, 256>>>(p_pool, rdkit, p_min, G);
    }

    // ---- MLP (fp32 SIMT; small) ----
    gemm_kernel<64, 64, 8, 4, 8, true, 1><<<dim3(G / 64, H1 / 64), 128>>>(
        p_min, mw1, mb1, p_m1, G, KMLP1, H1);
    gemm_kernel<64, 64, 8, 4, 8, true, 1><<<dim3(G / 64, H2 / 64), 128>>>(
        p_m1, mw2, mb2, p_m2, G, H1, H2);
    final_dot_kernel<<<(G * 32 + 255) / 256, 256>>>(p_m2, mw3, mb3, out, G);

    (void)n_in; (void)out_size;
}